// round 2
// baseline (speedup 1.0000x reference)
#include <cuda_runtime.h>
#include <math.h>

// ----------------------------------------------------------------------------
// SelfAttention: B=8, S=2048, D=768, fp32.
//   Q = Z @ Wq^T + bq ; K = Z @ Wk^T + bk ; V = Z @ Wv^T + bv
//   S = (Q @ K^T) / sqrt(D) ; P = softmax_rows(S) ; out = P @ V
// R1: fp32 tiled SGEMM (128x128x8, 8x8 microtile, 256 thr), DOUBLE-BUFFERED
//     smem with register-staged prefetch (1 sync per k-tile), + row softmax.
// ----------------------------------------------------------------------------

#define BATCH 8
#define SEQ   2048
#define DIM   768

#define BM 128
#define BN 128
#define BK 8
#define TM 8
#define TN 8

// Scratch (device globals: allocation-free per harness rules)
__device__ float g_Q[(size_t)BATCH * SEQ * DIM];
__device__ float g_K[(size_t)BATCH * SEQ * DIM];
__device__ float g_V[(size_t)BATCH * SEQ * DIM];
__device__ float g_S[(size_t)BATCH * SEQ * SEQ];

// BMODE: 0 -> C = A[M,K] @ B[K,N]        (NN)
//        1 -> C = A[M,K] @ B[N,K]^T      (NT)
// EPI:   0 -> C = acc*alpha + bias[n]
//        1 -> C = acc*alpha
template<int BMODE, int EPI>
__global__ __launch_bounds__(256, 2)
void gemm_k(const float* __restrict__ A, const float* __restrict__ B,
            const float* __restrict__ bias, float alpha, float* __restrict__ C,
            int M, int N, int K,
            size_t sA, size_t sB, size_t sC)
{
    A += (size_t)blockIdx.z * sA;
    B += (size_t)blockIdx.z * sB;
    C += (size_t)blockIdx.z * sC;

    __shared__ float As[2][BK][BM];
    __shared__ float Bs[2][BK][BN];

    const int tid = threadIdx.x;
    const int tx  = tid & 15;   // N dir (8 cols each)
    const int ty  = tid >> 4;   // M dir (8 rows each)

    // A tile load: 128 rows x 8 cols, one float4 per thread along K
    const int aRow  = tid >> 1;          // 0..127
    const int aCol4 = (tid & 1) * 4;     // 0 or 4
    // B tile load (NN): 8 rows x 128 cols, one float4 per thread along N
    const int bK  = tid >> 5;            // 0..7
    const int bN4 = (tid & 31) * 4;      // 0..124

    const float* Abase = A + (size_t)(blockIdx.y * BM + aRow) * K + aCol4;
    const float* BbaseNT = B + (size_t)(blockIdx.x * BN + aRow) * K + aCol4;
    const float* BbaseNN = B + (size_t)(blockIdx.x * BN + bN4);

    float acc[TM][TN];
    #pragma unroll
    for (int i = 0; i < TM; i++)
        #pragma unroll
        for (int j = 0; j < TN; j++) acc[i][j] = 0.f;

    // --- prologue: tile 0 straight into buffer 0 ---
    {
        float4 av = *(const float4*)(Abase);
        As[0][aCol4 + 0][aRow] = av.x;
        As[0][aCol4 + 1][aRow] = av.y;
        As[0][aCol4 + 2][aRow] = av.z;
        As[0][aCol4 + 3][aRow] = av.w;
        if (BMODE == 1) {
            float4 bv = *(const float4*)(BbaseNT);
            Bs[0][aCol4 + 0][aRow] = bv.x;
            Bs[0][aCol4 + 1][aRow] = bv.y;
            Bs[0][aCol4 + 2][aRow] = bv.z;
            Bs[0][aCol4 + 3][aRow] = bv.w;
        } else {
            *(float4*)&Bs[0][bK][bN4] =
                *(const float4*)(BbaseNN + (size_t)bK * N);
        }
    }
    __syncthreads();

    const int nT = K / BK;
    for (int t = 0; t < nT; t++) {
        const int buf = t & 1;
        const bool hasNext = (t + 1 < nT);

        // --- prefetch next tile into registers (issue LDGs before compute) ---
        float4 pa, pb;
        if (hasNext) {
            const int k0 = (t + 1) * BK;
            pa = *(const float4*)(Abase + k0);
            if (BMODE == 1)
                pb = *(const float4*)(BbaseNT + k0);
            else
                pb = *(const float4*)(BbaseNN + (size_t)(k0 + bK) * N);
        }

        // --- compute from current buffer ---
        #pragma unroll
        for (int kk = 0; kk < BK; kk++) {
            float ar[TM], br[TN];
            #pragma unroll
            for (int i = 0; i < TM; i++) ar[i] = As[buf][kk][ty * TM + i];
            #pragma unroll
            for (int j = 0; j < TN; j++) br[j] = Bs[buf][kk][tx * TN + j];
            #pragma unroll
            for (int i = 0; i < TM; i++)
                #pragma unroll
                for (int j = 0; j < TN; j++)
                    acc[i][j] = fmaf(ar[i], br[j], acc[i][j]);
        }

        // --- store prefetched tile into the other buffer ---
        if (hasNext) {
            const int nb = buf ^ 1;
            As[nb][aCol4 + 0][aRow] = pa.x;
            As[nb][aCol4 + 1][aRow] = pa.y;
            As[nb][aCol4 + 2][aRow] = pa.z;
            As[nb][aCol4 + 3][aRow] = pa.w;
            if (BMODE == 1) {
                Bs[nb][aCol4 + 0][aRow] = pb.x;
                Bs[nb][aCol4 + 1][aRow] = pb.y;
                Bs[nb][aCol4 + 2][aRow] = pb.z;
                Bs[nb][aCol4 + 3][aRow] = pb.w;
            } else {
                *(float4*)&Bs[nb][bK][bN4] = pb;
            }
        }
        __syncthreads();
    }

    // --- epilogue ---
    const int cn0 = blockIdx.x * BN + tx * TN;
    #pragma unroll
    for (int i = 0; i < TM; i++) {
        const size_t row = (size_t)(blockIdx.y * BM + ty * TM + i);
        float* Cp = C + row * N + cn0;
        #pragma unroll
        for (int j = 0; j < TN; j += 4) {
            float4 v;
            v.x = acc[i][j + 0] * alpha;
            v.y = acc[i][j + 1] * alpha;
            v.z = acc[i][j + 2] * alpha;
            v.w = acc[i][j + 3] * alpha;
            if (EPI == 0) {
                v.x += bias[cn0 + j + 0];
                v.y += bias[cn0 + j + 1];
                v.z += bias[cn0 + j + 2];
                v.w += bias[cn0 + j + 3];
            }
            *(float4*)(Cp + j) = v;
        }
    }
}

// ---------------------------------------------------------------------------
// Row softmax over SEQ=2048 columns; one 256-thread block per row.
// Row values live in registers (8 per thread) between passes.
// ---------------------------------------------------------------------------
__device__ __forceinline__ float blockMax(float v) {
    __shared__ float sm[8];
    __shared__ float res;
    #pragma unroll
    for (int o = 16; o; o >>= 1) v = fmaxf(v, __shfl_xor_sync(0xffffffffu, v, o));
    if ((threadIdx.x & 31) == 0) sm[threadIdx.x >> 5] = v;
    __syncthreads();
    if (threadIdx.x == 0) {
        float m = sm[0];
        #pragma unroll
        for (int w = 1; w < 8; w++) m = fmaxf(m, sm[w]);
        res = m;
    }
    __syncthreads();
    return res;
}

__device__ __forceinline__ float blockSum(float v) {
    __shared__ float sm[8];
    __shared__ float res;
    #pragma unroll
    for (int o = 16; o; o >>= 1) v += __shfl_xor_sync(0xffffffffu, v, o);
    if ((threadIdx.x & 31) == 0) sm[threadIdx.x >> 5] = v;
    __syncthreads();
    if (threadIdx.x == 0) {
        float s = 0.f;
        #pragma unroll
        for (int w = 0; w < 8; w++) s += sm[w];
        res = s;
    }
    __syncthreads();
    return res;
}

__global__ __launch_bounds__(256)
void softmax_k(float* __restrict__ S)
{
    float* row = S + (size_t)blockIdx.x * SEQ;
    float v[8];
    #pragma unroll
    for (int i = 0; i < 8; i++) v[i] = row[threadIdx.x + i * 256];

    float m = -3.402823466e38f;
    #pragma unroll
    for (int i = 0; i < 8; i++) m = fmaxf(m, v[i]);
    m = blockMax(m);

    float s = 0.f;
    #pragma unroll
    for (int i = 0; i < 8; i++) { v[i] = __expf(v[i] - m); s += v[i]; }
    s = blockSum(s);

    const float inv = 1.f / s;
    #pragma unroll
    for (int i = 0; i < 8; i++) row[threadIdx.x + i * 256] = v[i] * inv;
}

// ---------------------------------------------------------------------------
extern "C" void kernel_launch(void* const* d_in, const int* in_sizes, int n_in,
                              void* d_out, int out_size)
{
    (void)in_sizes; (void)n_in; (void)out_size;
    const float* Z  = (const float*)d_in[0];
    const float* Wq = (const float*)d_in[1];
    const float* bq = (const float*)d_in[2];
    const float* Wk = (const float*)d_in[3];
    const float* bk = (const float*)d_in[4];
    const float* Wv = (const float*)d_in[5];
    const float* bv = (const float*)d_in[6];
    float* out = (float*)d_out;

    float *Q, *Kp, *V, *Sc;
    cudaGetSymbolAddress((void**)&Q,  g_Q);
    cudaGetSymbolAddress((void**)&Kp, g_K);
    cudaGetSymbolAddress((void**)&V,  g_V);
    cudaGetSymbolAddress((void**)&Sc, g_S);

    const dim3 blk(256);
    const float scale = 1.f / sqrtf((float)DIM);
    const size_t sQKV = (size_t)SEQ * DIM;   // per-batch Q/K/V stride
    const size_t sS   = (size_t)SEQ * SEQ;   // per-batch scores stride

    // 1) QKV projections: [16384,768] @ [768,768]^T + bias  (NT, bias epilogue)
    {
        dim3 g(DIM / BN, (BATCH * SEQ) / BM, 1);
        gemm_k<1, 0><<<g, blk>>>(Z, Wq, bq, 1.f, Q,  BATCH * SEQ, DIM, DIM, 0, 0, 0);
        gemm_k<1, 0><<<g, blk>>>(Z, Wk, bk, 1.f, Kp, BATCH * SEQ, DIM, DIM, 0, 0, 0);
        gemm_k<1, 0><<<g, blk>>>(Z, Wv, bv, 1.f, V,  BATCH * SEQ, DIM, DIM, 0, 0, 0);
    }

    // 2) scores = Q @ K^T * scale  (NT, batched over z)
    {
        dim3 g(SEQ / BN, SEQ / BM, BATCH);
        gemm_k<1, 1><<<g, blk>>>(Q, Kp, nullptr, scale, Sc,
                                 SEQ, SEQ, DIM, sQKV, sQKV, sS);
    }

    // 3) row softmax
    softmax_k<<<BATCH * SEQ, 256>>>(Sc);

    // 4) out = P @ V  (NN, batched over z)
    {
        dim3 g(DIM / BN, SEQ / BM, BATCH);
        gemm_k<0, 1><<<g, blk>>>(Sc, V, nullptr, 1.f, out,
                                 SEQ, DIM, SEQ, sS, sQKV, sQKV);
    }
}

// round 5
// speedup vs baseline: 2.5465x; 2.5465x over previous
#include <cuda_runtime.h>
#include <cuda_bf16.h>
#include <cstdint>
#include <math.h>

// ============================================================================
// SelfAttention B=8, S=2048, D=768 fp32 — bf16 split (hi/lo, 3-term) on the
// LEGACY tensor path (mma.sync.m16n8k16.bf16 + ldmatrix + cp.async), since the
// harness compiles at virtual arch compute_100 (no tcgen05).
//   1) Q' = (Z Wq^T + bq)*scale ; K = Z Wk^T + bk      [mode 0]
//      Vt = Wv Z^T + bv[row]  (transposed directly)    [mode 1]
//   2) S = Q' K^T                                      [mode 2, fp32 out]
//   3) row softmax -> split-bf16 P
//   4) out = P (Vt)^T                                  [mode 2, fp32 out]
// All four GEMMs: one NT K-major kernel, 128x128 tile, BK=32, cp.async
// double buffer, 8 warps, warp tile 32x64, 3 MMA terms per k16.
// ============================================================================

#define BATCH 8
#define SEQ   2048
#define DIM   768
#define MROWS (BATCH * SEQ)      // 16384
#define BK    32                 // k-chunk (32 bf16 = 64B rows, SW64 swizzle)
#define ARR_B 8192               // 128 rows * 32 bf16 * 2B
#define BUF_B (4 * ARR_B)        // Ah, Al, Bh, Bl
#define SMEM_BYTES (2 * BUF_B)   // 64 KB double buffered

// ---------------- device scratch (allocation-free rules) ----------------
__device__ __align__(256) __nv_bfloat16 g_Zh[(size_t)MROWS * DIM];
__device__ __align__(256) __nv_bfloat16 g_Zl[(size_t)MROWS * DIM];
__device__ __align__(256) __nv_bfloat16 g_Wh[3][(size_t)DIM * DIM];
__device__ __align__(256) __nv_bfloat16 g_Wl[3][(size_t)DIM * DIM];
__device__ __align__(256) __nv_bfloat16 g_Qh[(size_t)MROWS * DIM];
__device__ __align__(256) __nv_bfloat16 g_Ql[(size_t)MROWS * DIM];
__device__ __align__(256) __nv_bfloat16 g_Kh[(size_t)MROWS * DIM];
__device__ __align__(256) __nv_bfloat16 g_Kl[(size_t)MROWS * DIM];
__device__ __align__(256) __nv_bfloat16 g_Vth[(size_t)DIM * MROWS];  // [768,16384]
__device__ __align__(256) __nv_bfloat16 g_Vtl[(size_t)DIM * MROWS];
__device__ __align__(256) float         g_S [(size_t)BATCH * SEQ * SEQ];
__device__ __align__(256) __nv_bfloat16 g_Ph[(size_t)BATCH * SEQ * SEQ];
__device__ __align__(256) __nv_bfloat16 g_Pl[(size_t)BATCH * SEQ * SEQ];

// ---------------- PTX helpers (all base-ISA, compile at compute_100) --------
__device__ __forceinline__ uint32_t smem_u32(const void* p) {
    uint32_t a;
    asm("{ .reg .u64 t; cvta.to.shared.u64 t, %1; cvt.u32.u64 %0, t; }"
        : "=r"(a) : "l"(p));
    return a;
}
__device__ __forceinline__ void cp16(uint32_t saddr, const void* gaddr) {
    asm volatile("cp.async.cg.shared.global [%0], [%1], 16;"
                 :: "r"(saddr), "l"(gaddr));
}
#define CP_COMMIT() asm volatile("cp.async.commit_group;" ::: "memory")
template<int N>
__device__ __forceinline__ void cp_wait() {
    asm volatile("cp.async.wait_group %0;" :: "n"(N) : "memory");
}
__device__ __forceinline__ void ldsm4(uint32_t* r, uint32_t addr) {
    asm volatile("ldmatrix.sync.aligned.m8n8.x4.shared.b16 {%0,%1,%2,%3}, [%4];"
                 : "=r"(r[0]), "=r"(r[1]), "=r"(r[2]), "=r"(r[3]) : "r"(addr));
}
__device__ __forceinline__ void mma16816(float* d, const uint32_t* a,
                                         uint32_t b0, uint32_t b1) {
    asm volatile(
        "mma.sync.aligned.m16n8k16.row.col.f32.bf16.bf16.f32 "
        "{%0,%1,%2,%3}, {%4,%5,%6,%7}, {%8,%9}, {%0,%1,%2,%3};"
        : "+f"(d[0]), "+f"(d[1]), "+f"(d[2]), "+f"(d[3])
        : "r"(a[0]), "r"(a[1]), "r"(a[2]), "r"(a[3]), "r"(b0), "r"(b1));
}

// ---------------- split helpers ----------------
__device__ __forceinline__ void split2(float x, __nv_bfloat16& h, __nv_bfloat16& l) {
    h = __float2bfloat16(x);
    l = __float2bfloat16(x - __bfloat162float(h));
}

__global__ __launch_bounds__(256)
void split_k(const float4* __restrict__ in, __nv_bfloat162* __restrict__ h,
             __nv_bfloat162* __restrict__ l, int n4)
{
    int i = blockIdx.x * 256 + threadIdx.x;
    if (i >= n4) return;
    float4 x = in[i];
    __nv_bfloat16 h0, h1, h2, h3, l0, l1, l2, l3;
    split2(x.x, h0, l0); split2(x.y, h1, l1);
    split2(x.z, h2, l2); split2(x.w, h3, l3);
    __nv_bfloat162 a; a.x = h0; a.y = h1;
    __nv_bfloat162 b; b.x = h2; b.y = h3;
    __nv_bfloat162 c; c.x = l0; c.y = l1;
    __nv_bfloat162 d; d.x = l2; d.y = l3;
    h[2 * i] = a; h[2 * i + 1] = b;
    l[2 * i] = c; l[2 * i + 1] = d;
}

// swizzled smem offset for 64B rows: seg' = seg ^ ((row>>1)&3)
__device__ __forceinline__ uint32_t sw_off(int row, int seg) {
    return (uint32_t)row * 64u + (uint32_t)((seg ^ ((row >> 1) & 3)) * 16);
}

// ============================================================================
// split-bf16 NT GEMM: C[M,N] = (Ah+Al)[M,K] x ((Bh+Bl)[N,K])^T
// MODE 0: C -> bf16 hi/lo, x = (acc + bias[col]) * alpha
// MODE 1: C -> bf16 hi/lo, x = (acc + bias[row]) * alpha
// MODE 2: C -> fp32,        x = acc
// ============================================================================
template<int MODE>
__global__ __launch_bounds__(256, 1)
void mma_gemm(const __nv_bfloat16* __restrict__ Ah, const __nv_bfloat16* __restrict__ Al,
              int ldA, size_t sA,
              const __nv_bfloat16* __restrict__ Bh, const __nv_bfloat16* __restrict__ Bl,
              int ldB, size_t sB,
              const float* __restrict__ bias, float alpha,
              __nv_bfloat16* __restrict__ Ch, __nv_bfloat16* __restrict__ Cl,
              float* __restrict__ Cf, int ldC, size_t sC, int Ktot)
{
    extern __shared__ __align__(1024) char smem[];
    const uint32_t su = smem_u32(smem);
    const int tid  = threadIdx.x;
    const int wid  = tid >> 5;
    const int lane = tid & 31;
    const int z    = blockIdx.z;

    Ah += (size_t)z * sA;  Al += (size_t)z * sA;
    Bh += (size_t)z * sB;  Bl += (size_t)z * sB;

    const __nv_bfloat16* gAh = Ah + (size_t)(blockIdx.y * 128) * ldA;
    const __nv_bfloat16* gAl = Al + (size_t)(blockIdx.y * 128) * ldA;
    const __nv_bfloat16* gBh = Bh + (size_t)(blockIdx.x * 128) * ldB;
    const __nv_bfloat16* gBl = Bl + (size_t)(blockIdx.x * 128) * ldB;

    // ---- cp.async loader: 128 rows x 4 x 16B segs per array, 2 per thread ----
    const int seg = tid & 3;       // 16B segment (8 bf16) within 64B row
    const int r0  = tid >> 2;      // rows r0, r0+64
    auto issue_chunk = [&](int k0, int buf) {
        const uint32_t base = su + (uint32_t)buf * BUF_B;
        #pragma unroll
        for (int i = 0; i < 2; i++) {
            const int r = r0 + 64 * i;
            const uint32_t so = sw_off(r, seg);
            const size_t oa = (size_t)r * ldA + k0 + seg * 8;
            const size_t ob = (size_t)r * ldB + k0 + seg * 8;
            cp16(base + 0 * ARR_B + so, gAh + oa);
            cp16(base + 1 * ARR_B + so, gAl + oa);
            cp16(base + 2 * ARR_B + so, gBh + ob);
            cp16(base + 3 * ARR_B + so, gBl + ob);
        }
    };

    // ---- warp tiling: 4 warps on M (32 rows each), 2 on N (64 cols each) ----
    const int warpM = (wid & 3) * 32;
    const int warpN = (wid >> 2) * 64;
    // ldmatrix lane roles
    const int laneA_row = lane & 15;          // + warpM + mt*16
    const int laneA_kh  = lane >> 4;          // k half (0/1)
    const int laneB_row = ((lane >> 4) << 3) + (lane & 7);  // + warpN + g*16
    const int laneB_kh  = (lane >> 3) & 1;

    float acc[2][8][4];
    #pragma unroll
    for (int mt = 0; mt < 2; mt++)
        #pragma unroll
        for (int nt = 0; nt < 8; nt++)
            #pragma unroll
            for (int e = 0; e < 4; e++) acc[mt][nt][e] = 0.f;

    const int nCh = Ktot / BK;
    issue_chunk(0, 0);
    CP_COMMIT();

    for (int t = 0; t < nCh; t++) {
        const int b = t & 1;
        if (t + 1 < nCh) {
            issue_chunk((t + 1) * BK, b ^ 1);
            CP_COMMIT();
            cp_wait<1>();
        } else {
            cp_wait<0>();
        }
        __syncthreads();

        const uint32_t base = su + (uint32_t)b * BUF_B;
        #pragma unroll
        for (int ks = 0; ks < 2; ks++) {
            uint32_t aH[2][4], aL[2][4];
            #pragma unroll
            for (int mt = 0; mt < 2; mt++) {
                const int rA = warpM + mt * 16 + laneA_row;
                const int sA2 = ks * 2 + laneA_kh;
                ldsm4(aH[mt], base + 0 * ARR_B + sw_off(rA, sA2));
                ldsm4(aL[mt], base + 1 * ARR_B + sw_off(rA, sA2));
            }
            #pragma unroll
            for (int g = 0; g < 4; g++) {
                uint32_t bH[4], bL[4];
                const int rB = warpN + g * 16 + laneB_row;
                const int sB2 = ks * 2 + laneB_kh;
                ldsm4(bH, base + 2 * ARR_B + sw_off(rB, sB2));
                ldsm4(bL, base + 3 * ARR_B + sw_off(rB, sB2));
                #pragma unroll
                for (int mt = 0; mt < 2; mt++) {
                    mma16816(acc[mt][2 * g + 0], aH[mt], bH[0], bH[1]);
                    mma16816(acc[mt][2 * g + 1], aH[mt], bH[2], bH[3]);
                    mma16816(acc[mt][2 * g + 0], aL[mt], bH[0], bH[1]);
                    mma16816(acc[mt][2 * g + 1], aL[mt], bH[2], bH[3]);
                    mma16816(acc[mt][2 * g + 0], aH[mt], bL[0], bL[1]);
                    mma16816(acc[mt][2 * g + 1], aH[mt], bL[2], bL[3]);
                }
            }
        }
        __syncthreads();
    }

    // ---- epilogue: frag (mt,nt): rows warpM+mt*16+(lane>>2)(+8), cols +0/1 ----
    const int erow = lane >> 2;
    const int ecol = (lane & 3) * 2;
    #pragma unroll
    for (int mt = 0; mt < 2; mt++) {
        #pragma unroll
        for (int half = 0; half < 2; half++) {        // d01 (row) / d23 (row+8)
            const size_t mg = (size_t)blockIdx.y * 128 + warpM + mt * 16 + erow + half * 8;
            const float rowbias = (MODE == 1) ? bias[mg] : 0.f;
            #pragma unroll
            for (int nt = 0; nt < 8; nt++) {
                const int n0 = blockIdx.x * 128 + warpN + nt * 8 + ecol;
                float x0 = acc[mt][nt][half * 2 + 0];
                float x1 = acc[mt][nt][half * 2 + 1];
                if (MODE == 2) {
                    float2 v; v.x = x0; v.y = x1;
                    *(float2*)(Cf + (size_t)z * sC + mg * ldC + n0) = v;
                } else {
                    if (MODE == 0) {
                        x0 = (x0 + bias[n0 + 0]) * alpha;
                        x1 = (x1 + bias[n0 + 1]) * alpha;
                    } else {
                        x0 = (x0 + rowbias) * alpha;
                        x1 = (x1 + rowbias) * alpha;
                    }
                    __nv_bfloat16 h0, h1, l0, l1;
                    split2(x0, h0, l0); split2(x1, h1, l1);
                    __nv_bfloat162 hv; hv.x = h0; hv.y = h1;
                    __nv_bfloat162 lv; lv.x = l0; lv.y = l1;
                    *(__nv_bfloat162*)(Ch + (size_t)z * sC + mg * ldC + n0) = hv;
                    *(__nv_bfloat162*)(Cl + (size_t)z * sC + mg * ldC + n0) = lv;
                }
            }
        }
    }
}

// ============================================================================
// softmax over rows of g_S (fp32), writes split-bf16 P
// ============================================================================
__global__ __launch_bounds__(256)
void softmax_k(const float* __restrict__ S, __nv_bfloat16* __restrict__ Ph,
               __nv_bfloat16* __restrict__ Pl)
{
    __shared__ float red[8];
    __shared__ float resv;
    const int tid = threadIdx.x;
    const float* row = S + (size_t)blockIdx.x * SEQ;

    float4 a = *(const float4*)(row + tid * 8);
    float4 b = *(const float4*)(row + tid * 8 + 4);
    float v[8] = {a.x, a.y, a.z, a.w, b.x, b.y, b.z, b.w};

    float m = v[0];
    #pragma unroll
    for (int i = 1; i < 8; i++) m = fmaxf(m, v[i]);
    #pragma unroll
    for (int o = 16; o; o >>= 1) m = fmaxf(m, __shfl_xor_sync(0xffffffffu, m, o));
    if ((tid & 31) == 0) red[tid >> 5] = m;
    __syncthreads();
    if (tid == 0) {
        float t = red[0];
        #pragma unroll
        for (int w = 1; w < 8; w++) t = fmaxf(t, red[w]);
        resv = t;
    }
    __syncthreads();
    m = resv;

    float s = 0.f;
    #pragma unroll
    for (int i = 0; i < 8; i++) { v[i] = __expf(v[i] - m); s += v[i]; }
    #pragma unroll
    for (int o = 16; o; o >>= 1) s += __shfl_xor_sync(0xffffffffu, s, o);
    __syncthreads();
    if ((tid & 31) == 0) red[tid >> 5] = s;
    __syncthreads();
    if (tid == 0) {
        float t = 0.f;
        #pragma unroll
        for (int w = 0; w < 8; w++) t += red[w];
        resv = t;
    }
    __syncthreads();
    const float inv = 1.f / resv;

    __nv_bfloat16 hh[8], ll[8];
    #pragma unroll
    for (int i = 0; i < 8; i++) split2(v[i] * inv, hh[i], ll[i]);
    uint4 hv, lv;
    __nv_bfloat162 t0, t1, t2, t3;
    t0.x = hh[0]; t0.y = hh[1]; t1.x = hh[2]; t1.y = hh[3];
    t2.x = hh[4]; t2.y = hh[5]; t3.x = hh[6]; t3.y = hh[7];
    hv.x = *(uint32_t*)&t0; hv.y = *(uint32_t*)&t1;
    hv.z = *(uint32_t*)&t2; hv.w = *(uint32_t*)&t3;
    t0.x = ll[0]; t0.y = ll[1]; t1.x = ll[2]; t1.y = ll[3];
    t2.x = ll[4]; t2.y = ll[5]; t3.x = ll[6]; t3.y = ll[7];
    lv.x = *(uint32_t*)&t0; lv.y = *(uint32_t*)&t1;
    lv.z = *(uint32_t*)&t2; lv.w = *(uint32_t*)&t3;
    *(uint4*)(Ph + (size_t)blockIdx.x * SEQ + tid * 8) = hv;
    *(uint4*)(Pl + (size_t)blockIdx.x * SEQ + tid * 8) = lv;
}

// ============================================================================
extern "C" void kernel_launch(void* const* d_in, const int* in_sizes, int n_in,
                              void* d_out, int out_size)
{
    (void)in_sizes; (void)n_in; (void)out_size;
    const float* Z  = (const float*)d_in[0];
    const float* Wq = (const float*)d_in[1];
    const float* bq = (const float*)d_in[2];
    const float* Wk = (const float*)d_in[3];
    const float* bk = (const float*)d_in[4];
    const float* Wv = (const float*)d_in[5];
    const float* bv = (const float*)d_in[6];
    float* out = (float*)d_out;

    __nv_bfloat16 *Zh, *Zl, *Wh, *Wl, *Qh, *Ql, *Kh, *Kl, *Vth, *Vtl, *Ph, *Pl;
    float* Sc;
    cudaGetSymbolAddress((void**)&Zh,  g_Zh);
    cudaGetSymbolAddress((void**)&Zl,  g_Zl);
    cudaGetSymbolAddress((void**)&Wh,  g_Wh);
    cudaGetSymbolAddress((void**)&Wl,  g_Wl);
    cudaGetSymbolAddress((void**)&Qh,  g_Qh);
    cudaGetSymbolAddress((void**)&Ql,  g_Ql);
    cudaGetSymbolAddress((void**)&Kh,  g_Kh);
    cudaGetSymbolAddress((void**)&Kl,  g_Kl);
    cudaGetSymbolAddress((void**)&Vth, g_Vth);
    cudaGetSymbolAddress((void**)&Vtl, g_Vtl);
    cudaGetSymbolAddress((void**)&Ph,  g_Ph);
    cudaGetSymbolAddress((void**)&Pl,  g_Pl);
    cudaGetSymbolAddress((void**)&Sc,  g_S);

    cudaFuncSetAttribute(mma_gemm<0>, cudaFuncAttributeMaxDynamicSharedMemorySize, SMEM_BYTES);
    cudaFuncSetAttribute(mma_gemm<1>, cudaFuncAttributeMaxDynamicSharedMemorySize, SMEM_BYTES);
    cudaFuncSetAttribute(mma_gemm<2>, cudaFuncAttributeMaxDynamicSharedMemorySize, SMEM_BYTES);

    const float scale = 1.f / sqrtf((float)DIM);
    const size_t WSZ = (size_t)DIM * DIM;

    // 0) split inputs to bf16 hi/lo
    {
        int n4 = (MROWS * DIM) / 4;
        split_k<<<(n4 + 255) / 256, 256>>>((const float4*)Z,
            (__nv_bfloat162*)Zh, (__nv_bfloat162*)Zl, n4);
        int w4 = (DIM * DIM) / 4;
        split_k<<<(w4 + 255) / 256, 256>>>((const float4*)Wq,
            (__nv_bfloat162*)(Wh + 0 * WSZ), (__nv_bfloat162*)(Wl + 0 * WSZ), w4);
        split_k<<<(w4 + 255) / 256, 256>>>((const float4*)Wk,
            (__nv_bfloat162*)(Wh + 1 * WSZ), (__nv_bfloat162*)(Wl + 1 * WSZ), w4);
        split_k<<<(w4 + 255) / 256, 256>>>((const float4*)Wv,
            (__nv_bfloat162*)(Wh + 2 * WSZ), (__nv_bfloat162*)(Wl + 2 * WSZ), w4);
    }

    // 1) Q' = (Z Wq^T + bq)*scale ; K = Z Wk^T + bk   [mode 0]
    {
        dim3 g(DIM / 128, MROWS / 128, 1);
        mma_gemm<0><<<g, 256, SMEM_BYTES>>>(Zh, Zl, DIM, 0,
            Wh + 0 * WSZ, Wl + 0 * WSZ, DIM, 0, bq, scale,
            Qh, Ql, nullptr, DIM, 0, DIM);
        mma_gemm<0><<<g, 256, SMEM_BYTES>>>(Zh, Zl, DIM, 0,
            Wh + 1 * WSZ, Wl + 1 * WSZ, DIM, 0, bk, 1.f,
            Kh, Kl, nullptr, DIM, 0, DIM);
    }
    // 1v) Vt = Wv Z^T + bv[row]   [mode 1], Vt is [768, 16384]
    {
        dim3 g(MROWS / 128, DIM / 128, 1);
        mma_gemm<1><<<g, 256, SMEM_BYTES>>>(Wh + 2 * WSZ, Wl + 2 * WSZ, DIM, 0,
            Zh, Zl, DIM, 0, bv, 1.f,
            Vth, Vtl, nullptr, MROWS, 0, DIM);
    }
    // 2) scores = Q' K^T          [mode 2, fp32]
    {
        dim3 g(SEQ / 128, SEQ / 128, BATCH);
        mma_gemm<2><<<g, 256, SMEM_BYTES>>>(Qh, Ql, DIM, (size_t)SEQ * DIM,
            Kh, Kl, DIM, (size_t)SEQ * DIM, nullptr, 1.f,
            nullptr, nullptr, Sc, SEQ, (size_t)SEQ * SEQ, DIM);
    }
    // 3) softmax -> split-bf16 P
    softmax_k<<<BATCH * SEQ, 256>>>(Sc, Ph, Pl);

    // 4) out = P (Vt)^T           [mode 2, fp32]; batch selects Vt column band
    {
        dim3 g(DIM / 128, SEQ / 128, BATCH);
        mma_gemm<2><<<g, 256, SMEM_BYTES>>>(Ph, Pl, SEQ, (size_t)SEQ * SEQ,
            Vth, Vtl, MROWS, (size_t)SEQ, nullptr, 1.f,
            nullptr, nullptr, out, DIM, (size_t)SEQ * DIM, SEQ);
    }
}

// round 7
// speedup vs baseline: 2.7902x; 1.0957x over previous
#include <cuda_runtime.h>
#include <cuda_bf16.h>
#include <cstdint>
#include <math.h>

// ============================================================================
// SelfAttention B=8, S=2048, D=768 fp32 — bf16 split (hi/lo, 3-term) on the
// legacy tensor path (mma.sync.m16n8k16.bf16 + ldmatrix + cp.async).
// R6: 5-buffer / 3-in-flight cp.async pipeline, ONE barrier per k-chunk
//     (was: 2 buffers / 1 in flight / 2 barriers).
//   1) Q' = (Z Wq^T + bq)*scale ; K = Z Wk^T + bk      [mode 0]
//      Vt = Wv Z^T + bv[row]  (transposed directly)    [mode 1]
//   2) S = Q' K^T                                      [mode 2, fp32 out]
//   3) row softmax -> split-bf16 P
//   4) out = P (Vt)^T                                  [mode 2, fp32 out]
// ============================================================================

#define BATCH 8
#define SEQ   2048
#define DIM   768
#define MROWS (BATCH * SEQ)      // 16384
#define BK    32                 // k-chunk (32 bf16 = 64B rows)
#define ARR_B 8192               // 128 rows * 32 bf16 * 2B
#define BUF_B (4 * ARR_B)        // Ah, Al, Bh, Bl
#define NBUF  5                  // smem buffers
#define INFLIGHT 3               // cp.async chunks in flight
#define SMEM_BYTES (NBUF * BUF_B)   // 160 KB

// ---------------- device scratch (allocation-free rules) ----------------
__device__ __align__(256) __nv_bfloat16 g_Zh[(size_t)MROWS * DIM];
__device__ __align__(256) __nv_bfloat16 g_Zl[(size_t)MROWS * DIM];
__device__ __align__(256) __nv_bfloat16 g_Wh[3][(size_t)DIM * DIM];
__device__ __align__(256) __nv_bfloat16 g_Wl[3][(size_t)DIM * DIM];
__device__ __align__(256) __nv_bfloat16 g_Qh[(size_t)MROWS * DIM];
__device__ __align__(256) __nv_bfloat16 g_Ql[(size_t)MROWS * DIM];
__device__ __align__(256) __nv_bfloat16 g_Kh[(size_t)MROWS * DIM];
__device__ __align__(256) __nv_bfloat16 g_Kl[(size_t)MROWS * DIM];
__device__ __align__(256) __nv_bfloat16 g_Vth[(size_t)DIM * MROWS];  // [768,16384]
__device__ __align__(256) __nv_bfloat16 g_Vtl[(size_t)DIM * MROWS];
__device__ __align__(256) float         g_S [(size_t)BATCH * SEQ * SEQ];
__device__ __align__(256) __nv_bfloat16 g_Ph[(size_t)BATCH * SEQ * SEQ];
__device__ __align__(256) __nv_bfloat16 g_Pl[(size_t)BATCH * SEQ * SEQ];

// ---------------- PTX helpers (base ISA, compile at compute_100) --------
__device__ __forceinline__ uint32_t smem_u32(const void* p) {
    uint32_t a;
    asm("{ .reg .u64 t; cvta.to.shared.u64 t, %1; cvt.u32.u64 %0, t; }"
        : "=r"(a) : "l"(p));
    return a;
}
__device__ __forceinline__ void cp16(uint32_t saddr, const void* gaddr) {
    asm volatile("cp.async.cg.shared.global [%0], [%1], 16;"
                 :: "r"(saddr), "l"(gaddr));
}
#define CP_COMMIT() asm volatile("cp.async.commit_group;" ::: "memory")
template<int N>
__device__ __forceinline__ void cp_wait() {
    asm volatile("cp.async.wait_group %0;" :: "n"(N) : "memory");
}
__device__ __forceinline__ void ldsm4(uint32_t* r, uint32_t addr) {
    asm volatile("ldmatrix.sync.aligned.m8n8.x4.shared.b16 {%0,%1,%2,%3}, [%4];"
                 : "=r"(r[0]), "=r"(r[1]), "=r"(r[2]), "=r"(r[3]) : "r"(addr));
}
__device__ __forceinline__ void mma16816(float* d, const uint32_t* a,
                                         uint32_t b0, uint32_t b1) {
    asm volatile(
        "mma.sync.aligned.m16n8k16.row.col.f32.bf16.bf16.f32 "
        "{%0,%1,%2,%3}, {%4,%5,%6,%7}, {%8,%9}, {%0,%1,%2,%3};"
        : "+f"(d[0]), "+f"(d[1]), "+f"(d[2]), "+f"(d[3])
        : "r"(a[0]), "r"(a[1]), "r"(a[2]), "r"(a[3]), "r"(b0), "r"(b1));
}

// ---------------- split helpers ----------------
__device__ __forceinline__ void split2(float x, __nv_bfloat16& h, __nv_bfloat16& l) {
    h = __float2bfloat16(x);
    l = __float2bfloat16(x - __bfloat162float(h));
}

__global__ __launch_bounds__(256)
void split_k(const float4* __restrict__ in, __nv_bfloat162* __restrict__ h,
             __nv_bfloat162* __restrict__ l, int n4)
{
    int i = blockIdx.x * 256 + threadIdx.x;
    if (i >= n4) return;
    float4 x = in[i];
    __nv_bfloat16 h0, h1, h2, h3, l0, l1, l2, l3;
    split2(x.x, h0, l0); split2(x.y, h1, l1);
    split2(x.z, h2, l2); split2(x.w, h3, l3);
    __nv_bfloat162 a; a.x = h0; a.y = h1;
    __nv_bfloat162 b; b.x = h2; b.y = h3;
    __nv_bfloat162 c; c.x = l0; c.y = l1;
    __nv_bfloat162 d; d.x = l2; d.y = l3;
    h[2 * i] = a; h[2 * i + 1] = b;
    l[2 * i] = c; l[2 * i + 1] = d;
}

// swizzled smem offset for 64B rows: seg' = seg ^ ((row>>1)&3)
__device__ __forceinline__ uint32_t sw_off(int row, int seg) {
    return (uint32_t)row * 64u + (uint32_t)((seg ^ ((row >> 1) & 3)) * 16);
}

// ============================================================================
// split-bf16 NT GEMM: C[M,N] = (Ah+Al)[M,K] x ((Bh+Bl)[N,K])^T
// MODE 0: C -> bf16 hi/lo, x = (acc + bias[col]) * alpha
// MODE 1: C -> bf16 hi/lo, x = (acc + bias[row]) * alpha
// MODE 2: C -> fp32,        x = acc
// ============================================================================
template<int MODE>
__global__ __launch_bounds__(256, 1)
void mma_gemm(const __nv_bfloat16* __restrict__ Ah, const __nv_bfloat16* __restrict__ Al,
              int ldA, size_t sA,
              const __nv_bfloat16* __restrict__ Bh, const __nv_bfloat16* __restrict__ Bl,
              int ldB, size_t sB,
              const float* __restrict__ bias, float alpha,
              __nv_bfloat16* __restrict__ Ch, __nv_bfloat16* __restrict__ Cl,
              float* __restrict__ Cf, int ldC, size_t sC, int Ktot)
{
    extern __shared__ __align__(1024) char smem[];
    const uint32_t su = smem_u32(smem);
    const int tid  = threadIdx.x;
    const int wid  = tid >> 5;
    const int lane = tid & 31;
    const int z    = blockIdx.z;

    Ah += (size_t)z * sA;  Al += (size_t)z * sA;
    Bh += (size_t)z * sB;  Bl += (size_t)z * sB;

    const __nv_bfloat16* gAh = Ah + (size_t)(blockIdx.y * 128) * ldA;
    const __nv_bfloat16* gAl = Al + (size_t)(blockIdx.y * 128) * ldA;
    const __nv_bfloat16* gBh = Bh + (size_t)(blockIdx.x * 128) * ldB;
    const __nv_bfloat16* gBl = Bl + (size_t)(blockIdx.x * 128) * ldB;

    // ---- cp.async loader: 128 rows x 4 x 16B segs per array, 2 per thread ----
    const int seg = tid & 3;       // 16B segment (8 bf16) within 64B row
    const int r0  = tid >> 2;      // rows r0, r0+64
    auto issue_chunk = [&](int k0, int buf) {
        const uint32_t base = su + (uint32_t)buf * BUF_B;
        #pragma unroll
        for (int i = 0; i < 2; i++) {
            const int r = r0 + 64 * i;
            const uint32_t so = sw_off(r, seg);
            const size_t oa = (size_t)r * ldA + k0 + seg * 8;
            const size_t ob = (size_t)r * ldB + k0 + seg * 8;
            cp16(base + 0 * ARR_B + so, gAh + oa);
            cp16(base + 1 * ARR_B + so, gAl + oa);
            cp16(base + 2 * ARR_B + so, gBh + ob);
            cp16(base + 3 * ARR_B + so, gBl + ob);
        }
    };

    // ---- warp tiling: 4 warps on M (32 rows each), 2 on N (64 cols each) ----
    const int warpM = (wid & 3) * 32;
    const int warpN = (wid >> 2) * 64;
    // ldmatrix lane roles
    const int laneA_row = lane & 15;          // + warpM + mt*16
    const int laneA_kh  = lane >> 4;          // k half (0/1)
    const int laneB_row = ((lane >> 4) << 3) + (lane & 7);  // + warpN + g*16
    const int laneB_kh  = (lane >> 3) & 1;

    float acc[2][8][4];
    #pragma unroll
    for (int mt = 0; mt < 2; mt++)
        #pragma unroll
        for (int nt = 0; nt < 8; nt++)
            #pragma unroll
            for (int e = 0; e < 4; e++) acc[mt][nt][e] = 0.f;

    const int nCh = Ktot / BK;   // >= 24 for all stages (>= INFLIGHT)

    // ---- prologue: put INFLIGHT chunks in flight ----
    #pragma unroll
    for (int s = 0; s < INFLIGHT; s++) {
        issue_chunk(s * BK, s % NBUF);
        CP_COMMIT();
    }

    for (int t = 0; t < nCh; t++) {
        // issue chunk t+INFLIGHT (or empty commit to keep group count uniform)
        if (t + INFLIGHT < nCh)
            issue_chunk((t + INFLIGHT) * BK, (t + INFLIGHT) % NBUF);
        CP_COMMIT();
        cp_wait<INFLIGHT>();   // chunk t's group retired (3 newer may pend)
        __syncthreads();       // all threads' groups for chunk t visible

        const uint32_t base = su + (uint32_t)(t % NBUF) * BUF_B;
        #pragma unroll
        for (int ks = 0; ks < 2; ks++) {
            uint32_t aH[2][4], aL[2][4];
            #pragma unroll
            for (int mt = 0; mt < 2; mt++) {
                const int rA = warpM + mt * 16 + laneA_row;
                const int sA2 = ks * 2 + laneA_kh;
                ldsm4(aH[mt], base + 0 * ARR_B + sw_off(rA, sA2));
                ldsm4(aL[mt], base + 1 * ARR_B + sw_off(rA, sA2));
            }
            #pragma unroll
            for (int g = 0; g < 4; g++) {
                uint32_t bH[4], bL[4];
                const int rB = warpN + g * 16 + laneB_row;
                const int sB2 = ks * 2 + laneB_kh;
                ldsm4(bH, base + 2 * ARR_B + sw_off(rB, sB2));
                ldsm4(bL, base + 3 * ARR_B + sw_off(rB, sB2));
                #pragma unroll
                for (int mt = 0; mt < 2; mt++) {
                    mma16816(acc[mt][2 * g + 0], aH[mt], bH[0], bH[1]);
                    mma16816(acc[mt][2 * g + 1], aH[mt], bH[2], bH[3]);
                    mma16816(acc[mt][2 * g + 0], aL[mt], bH[0], bH[1]);
                    mma16816(acc[mt][2 * g + 1], aL[mt], bH[2], bH[3]);
                    mma16816(acc[mt][2 * g + 0], aH[mt], bL[0], bL[1]);
                    mma16816(acc[mt][2 * g + 1], aH[mt], bL[2], bL[3]);
                }
            }
        }
        // NO trailing __syncthreads(): with NBUF=5 > INFLIGHT=3, the buffer
        // written by iteration t's issue (chunk t+3 -> buf (t-2)%5) was last
        // read at iteration t-2, and every warp reaching this point passed the
        // iteration t-1 barrier, which proves all warps finished iteration
        // t-2's compute.
    }

    // ---- epilogue: frag (mt,nt): rows warpM+mt*16+(lane>>2)(+8), cols +0/1 ----
    const int erow = lane >> 2;
    const int ecol = (lane & 3) * 2;
    #pragma unroll
    for (int mt = 0; mt < 2; mt++) {
        #pragma unroll
        for (int half = 0; half < 2; half++) {        // d01 (row) / d23 (row+8)
            const size_t mg = (size_t)blockIdx.y * 128 + warpM + mt * 16 + erow + half * 8;
            const float rowbias = (MODE == 1) ? bias[mg] : 0.f;
            #pragma unroll
            for (int nt = 0; nt < 8; nt++) {
                const int n0 = blockIdx.x * 128 + warpN + nt * 8 + ecol;
                float x0 = acc[mt][nt][half * 2 + 0];
                float x1 = acc[mt][nt][half * 2 + 1];
                if (MODE == 2) {
                    float2 v; v.x = x0; v.y = x1;
                    *(float2*)(Cf + (size_t)z * sC + mg * ldC + n0) = v;
                } else {
                    if (MODE == 0) {
                        x0 = (x0 + bias[n0 + 0]) * alpha;
                        x1 = (x1 + bias[n0 + 1]) * alpha;
                    } else {
                        x0 = (x0 + rowbias) * alpha;
                        x1 = (x1 + rowbias) * alpha;
                    }
                    __nv_bfloat16 h0, h1, l0, l1;
                    split2(x0, h0, l0); split2(x1, h1, l1);
                    __nv_bfloat162 hv; hv.x = h0; hv.y = h1;
                    __nv_bfloat162 lv; lv.x = l0; lv.y = l1;
                    *(__nv_bfloat162*)(Ch + (size_t)z * sC + mg * ldC + n0) = hv;
                    *(__nv_bfloat162*)(Cl + (size_t)z * sC + mg * ldC + n0) = lv;
                }
            }
        }
    }
}

// ============================================================================
// softmax over rows of g_S (fp32), writes split-bf16 P
// ============================================================================
__global__ __launch_bounds__(256)
void softmax_k(const float* __restrict__ S, __nv_bfloat16* __restrict__ Ph,
               __nv_bfloat16* __restrict__ Pl)
{
    __shared__ float red[8];
    __shared__ float resv;
    const int tid = threadIdx.x;
    const float* row = S + (size_t)blockIdx.x * SEQ;

    float4 a = *(const float4*)(row + tid * 8);
    float4 b = *(const float4*)(row + tid * 8 + 4);
    float v[8] = {a.x, a.y, a.z, a.w, b.x, b.y, b.z, b.w};

    float m = v[0];
    #pragma unroll
    for (int i = 1; i < 8; i++) m = fmaxf(m, v[i]);
    #pragma unroll
    for (int o = 16; o; o >>= 1) m = fmaxf(m, __shfl_xor_sync(0xffffffffu, m, o));
    if ((tid & 31) == 0) red[tid >> 5] = m;
    __syncthreads();
    if (tid == 0) {
        float t = red[0];
        #pragma unroll
        for (int w = 1; w < 8; w++) t = fmaxf(t, red[w]);
        resv = t;
    }
    __syncthreads();
    m = resv;

    float s = 0.f;
    #pragma unroll
    for (int i = 0; i < 8; i++) { v[i] = __expf(v[i] - m); s += v[i]; }
    #pragma unroll
    for (int o = 16; o; o >>= 1) s += __shfl_xor_sync(0xffffffffu, s, o);
    __syncthreads();
    if ((tid & 31) == 0) red[tid >> 5] = s;
    __syncthreads();
    if (tid == 0) {
        float t = 0.f;
        #pragma unroll
        for (int w = 0; w < 8; w++) t += red[w];
        resv = t;
    }
    __syncthreads();
    const float inv = 1.f / resv;

    __nv_bfloat16 hh[8], ll[8];
    #pragma unroll
    for (int i = 0; i < 8; i++) split2(v[i] * inv, hh[i], ll[i]);
    uint4 hv, lv;
    __nv_bfloat162 t0, t1, t2, t3;
    t0.x = hh[0]; t0.y = hh[1]; t1.x = hh[2]; t1.y = hh[3];
    t2.x = hh[4]; t2.y = hh[5]; t3.x = hh[6]; t3.y = hh[7];
    hv.x = *(uint32_t*)&t0; hv.y = *(uint32_t*)&t1;
    hv.z = *(uint32_t*)&t2; hv.w = *(uint32_t*)&t3;
    t0.x = ll[0]; t0.y = ll[1]; t1.x = ll[2]; t1.y = ll[3];
    t2.x = ll[4]; t2.y = ll[5]; t3.x = ll[6]; t3.y = ll[7];
    lv.x = *(uint32_t*)&t0; lv.y = *(uint32_t*)&t1;
    lv.z = *(uint32_t*)&t2; lv.w = *(uint32_t*)&t3;
    *(uint4*)(Ph + (size_t)blockIdx.x * SEQ + tid * 8) = hv;
    *(uint4*)(Pl + (size_t)blockIdx.x * SEQ + tid * 8) = lv;
}

// ============================================================================
extern "C" void kernel_launch(void* const* d_in, const int* in_sizes, int n_in,
                              void* d_out, int out_size)
{
    (void)in_sizes; (void)n_in; (void)out_size;
    const float* Z  = (const float*)d_in[0];
    const float* Wq = (const float*)d_in[1];
    const float* bq = (const float*)d_in[2];
    const float* Wk = (const float*)d_in[3];
    const float* bk = (const float*)d_in[4];
    const float* Wv = (const float*)d_in[5];
    const float* bv = (const float*)d_in[6];
    float* out = (float*)d_out;

    __nv_bfloat16 *Zh, *Zl, *Wh, *Wl, *Qh, *Ql, *Kh, *Kl, *Vth, *Vtl, *Ph, *Pl;
    float* Sc;
    cudaGetSymbolAddress((void**)&Zh,  g_Zh);
    cudaGetSymbolAddress((void**)&Zl,  g_Zl);
    cudaGetSymbolAddress((void**)&Wh,  g_Wh);
    cudaGetSymbolAddress((void**)&Wl,  g_Wl);
    cudaGetSymbolAddress((void**)&Qh,  g_Qh);
    cudaGetSymbolAddress((void**)&Ql,  g_Ql);
    cudaGetSymbolAddress((void**)&Kh,  g_Kh);
    cudaGetSymbolAddress((void**)&Kl,  g_Kl);
    cudaGetSymbolAddress((void**)&Vth, g_Vth);
    cudaGetSymbolAddress((void**)&Vtl, g_Vtl);
    cudaGetSymbolAddress((void**)&Ph,  g_Ph);
    cudaGetSymbolAddress((void**)&Pl,  g_Pl);
    cudaGetSymbolAddress((void**)&Sc,  g_S);

    cudaFuncSetAttribute(mma_gemm<0>, cudaFuncAttributeMaxDynamicSharedMemorySize, SMEM_BYTES);
    cudaFuncSetAttribute(mma_gemm<1>, cudaFuncAttributeMaxDynamicSharedMemorySize, SMEM_BYTES);
    cudaFuncSetAttribute(mma_gemm<2>, cudaFuncAttributeMaxDynamicSharedMemorySize, SMEM_BYTES);

    const float scale = 1.f / sqrtf((float)DIM);
    const size_t WSZ = (size_t)DIM * DIM;

    // 0) split inputs to bf16 hi/lo
    {
        int n4 = (MROWS * DIM) / 4;
        split_k<<<(n4 + 255) / 256, 256>>>((const float4*)Z,
            (__nv_bfloat162*)Zh, (__nv_bfloat162*)Zl, n4);
        int w4 = (DIM * DIM) / 4;
        split_k<<<(w4 + 255) / 256, 256>>>((const float4*)Wq,
            (__nv_bfloat162*)(Wh + 0 * WSZ), (__nv_bfloat162*)(Wl + 0 * WSZ), w4);
        split_k<<<(w4 + 255) / 256, 256>>>((const float4*)Wk,
            (__nv_bfloat162*)(Wh + 1 * WSZ), (__nv_bfloat162*)(Wl + 1 * WSZ), w4);
        split_k<<<(w4 + 255) / 256, 256>>>((const float4*)Wv,
            (__nv_bfloat162*)(Wh + 2 * WSZ), (__nv_bfloat162*)(Wl + 2 * WSZ), w4);
    }

    // 1) Q' = (Z Wq^T + bq)*scale ; K = Z Wk^T + bk   [mode 0]
    {
        dim3 g(DIM / 128, MROWS / 128, 1);
        mma_gemm<0><<<g, 256, SMEM_BYTES>>>(Zh, Zl, DIM, 0,
            Wh + 0 * WSZ, Wl + 0 * WSZ, DIM, 0, bq, scale,
            Qh, Ql, nullptr, DIM, 0, DIM);
        mma_gemm<0><<<g, 256, SMEM_BYTES>>>(Zh, Zl, DIM, 0,
            Wh + 1 * WSZ, Wl + 1 * WSZ, DIM, 0, bk, 1.f,
            Kh, Kl, nullptr, DIM, 0, DIM);
    }
    // 1v) Vt = Wv Z^T + bv[row]   [mode 1], Vt is [768, 16384]
    {
        dim3 g(MROWS / 128, DIM / 128, 1);
        mma_gemm<1><<<g, 256, SMEM_BYTES>>>(Wh + 2 * WSZ, Wl + 2 * WSZ, DIM, 0,
            Zh, Zl, DIM, 0, bv, 1.f,
            Vth, Vtl, nullptr, MROWS, 0, DIM);
    }
    // 2) scores = Q' K^T          [mode 2, fp32]
    {
        dim3 g(SEQ / 128, SEQ / 128, BATCH);
        mma_gemm<2><<<g, 256, SMEM_BYTES>>>(Qh, Ql, DIM, (size_t)SEQ * DIM,
            Kh, Kl, DIM, (size_t)SEQ * DIM, nullptr, 1.f,
            nullptr, nullptr, Sc, SEQ, (size_t)SEQ * SEQ, DIM);
    }
    // 3) softmax -> split-bf16 P
    softmax_k<<<BATCH * SEQ, 256>>>(Sc, Ph, Pl);

    // 4) out = P (Vt)^T           [mode 2, fp32]; batch selects Vt column band
    {
        dim3 g(DIM / 128, SEQ / 128, BATCH);
        mma_gemm<2><<<g, 256, SMEM_BYTES>>>(Ph, Pl, SEQ, (size_t)SEQ * SEQ,
            Vth, Vtl, MROWS, (size_t)SEQ, nullptr, 1.f,
            nullptr, nullptr, out, DIM, (size_t)SEQ * DIM, SEQ);
    }
}

// round 8
// speedup vs baseline: 2.7907x; 1.0002x over previous
#include <cuda_runtime.h>
#include <cuda_bf16.h>
#include <cstdint>
#include <math.h>

// ============================================================================
// SelfAttention B=8, S=2048, D=768 fp32 — bf16 split (hi/lo, 3-term) on the
// legacy tensor path (mma.sync.m16n8k16.bf16 + ldmatrix + cp.async).
// R8: inner-loop restructure — hoist all 12 LDSM per k16 step, then issue the
//     48 HMMA grouped by term (16 distinct acc targets per group) so same-acc
//     RAW reuse distance goes 2 -> 16. Numerics bit-identical to R7.
// Pipeline (from R7): 5 buffers / 3 cp.async chunks in flight, 1 barrier/chunk.
// ============================================================================

#define BATCH 8
#define SEQ   2048
#define DIM   768
#define MROWS (BATCH * SEQ)      // 16384
#define BK    32                 // k-chunk (32 bf16 = 64B rows)
#define ARR_B 8192               // 128 rows * 32 bf16 * 2B
#define BUF_B (4 * ARR_B)        // Ah, Al, Bh, Bl
#define NBUF  5                  // smem buffers
#define INFLIGHT 3               // cp.async chunks in flight
#define SMEM_BYTES (NBUF * BUF_B)   // 160 KB

// ---------------- device scratch (allocation-free rules) ----------------
__device__ __align__(256) __nv_bfloat16 g_Zh[(size_t)MROWS * DIM];
__device__ __align__(256) __nv_bfloat16 g_Zl[(size_t)MROWS * DIM];
__device__ __align__(256) __nv_bfloat16 g_Wh[3][(size_t)DIM * DIM];
__device__ __align__(256) __nv_bfloat16 g_Wl[3][(size_t)DIM * DIM];
__device__ __align__(256) __nv_bfloat16 g_Qh[(size_t)MROWS * DIM];
__device__ __align__(256) __nv_bfloat16 g_Ql[(size_t)MROWS * DIM];
__device__ __align__(256) __nv_bfloat16 g_Kh[(size_t)MROWS * DIM];
__device__ __align__(256) __nv_bfloat16 g_Kl[(size_t)MROWS * DIM];
__device__ __align__(256) __nv_bfloat16 g_Vth[(size_t)DIM * MROWS];  // [768,16384]
__device__ __align__(256) __nv_bfloat16 g_Vtl[(size_t)DIM * MROWS];
__device__ __align__(256) float         g_S [(size_t)BATCH * SEQ * SEQ];
__device__ __align__(256) __nv_bfloat16 g_Ph[(size_t)BATCH * SEQ * SEQ];
__device__ __align__(256) __nv_bfloat16 g_Pl[(size_t)BATCH * SEQ * SEQ];

// ---------------- PTX helpers (base ISA, compile at compute_100) --------
__device__ __forceinline__ uint32_t smem_u32(const void* p) {
    uint32_t a;
    asm("{ .reg .u64 t; cvta.to.shared.u64 t, %1; cvt.u32.u64 %0, t; }"
        : "=r"(a) : "l"(p));
    return a;
}
__device__ __forceinline__ void cp16(uint32_t saddr, const void* gaddr) {
    asm volatile("cp.async.cg.shared.global [%0], [%1], 16;"
                 :: "r"(saddr), "l"(gaddr));
}
#define CP_COMMIT() asm volatile("cp.async.commit_group;" ::: "memory")
template<int N>
__device__ __forceinline__ void cp_wait() {
    asm volatile("cp.async.wait_group %0;" :: "n"(N) : "memory");
}
__device__ __forceinline__ void ldsm4(uint32_t* r, uint32_t addr) {
    asm volatile("ldmatrix.sync.aligned.m8n8.x4.shared.b16 {%0,%1,%2,%3}, [%4];"
                 : "=r"(r[0]), "=r"(r[1]), "=r"(r[2]), "=r"(r[3]) : "r"(addr));
}
__device__ __forceinline__ void mma16816(float* d, const uint32_t* a,
                                         uint32_t b0, uint32_t b1) {
    asm volatile(
        "mma.sync.aligned.m16n8k16.row.col.f32.bf16.bf16.f32 "
        "{%0,%1,%2,%3}, {%4,%5,%6,%7}, {%8,%9}, {%0,%1,%2,%3};"
        : "+f"(d[0]), "+f"(d[1]), "+f"(d[2]), "+f"(d[3])
        : "r"(a[0]), "r"(a[1]), "r"(a[2]), "r"(a[3]), "r"(b0), "r"(b1));
}

// ---------------- split helpers ----------------
__device__ __forceinline__ void split2(float x, __nv_bfloat16& h, __nv_bfloat16& l) {
    h = __float2bfloat16(x);
    l = __float2bfloat16(x - __bfloat162float(h));
}

__global__ __launch_bounds__(256)
void split_k(const float4* __restrict__ in, __nv_bfloat162* __restrict__ h,
             __nv_bfloat162* __restrict__ l, int n4)
{
    int i = blockIdx.x * 256 + threadIdx.x;
    if (i >= n4) return;
    float4 x = in[i];
    __nv_bfloat16 h0, h1, h2, h3, l0, l1, l2, l3;
    split2(x.x, h0, l0); split2(x.y, h1, l1);
    split2(x.z, h2, l2); split2(x.w, h3, l3);
    __nv_bfloat162 a; a.x = h0; a.y = h1;
    __nv_bfloat162 b; b.x = h2; b.y = h3;
    __nv_bfloat162 c; c.x = l0; c.y = l1;
    __nv_bfloat162 d; d.x = l2; d.y = l3;
    h[2 * i] = a; h[2 * i + 1] = b;
    l[2 * i] = c; l[2 * i + 1] = d;
}

// swizzled smem offset for 64B rows: seg' = seg ^ ((row>>1)&3)
__device__ __forceinline__ uint32_t sw_off(int row, int seg) {
    return (uint32_t)row * 64u + (uint32_t)((seg ^ ((row >> 1) & 3)) * 16);
}

// ============================================================================
// split-bf16 NT GEMM: C[M,N] = (Ah+Al)[M,K] x ((Bh+Bl)[N,K])^T
// MODE 0: C -> bf16 hi/lo, x = (acc + bias[col]) * alpha
// MODE 1: C -> bf16 hi/lo, x = (acc + bias[row]) * alpha
// MODE 2: C -> fp32,        x = acc
// ============================================================================
template<int MODE>
__global__ __launch_bounds__(256, 1)
void mma_gemm(const __nv_bfloat16* __restrict__ Ah, const __nv_bfloat16* __restrict__ Al,
              int ldA, size_t sA,
              const __nv_bfloat16* __restrict__ Bh, const __nv_bfloat16* __restrict__ Bl,
              int ldB, size_t sB,
              const float* __restrict__ bias, float alpha,
              __nv_bfloat16* __restrict__ Ch, __nv_bfloat16* __restrict__ Cl,
              float* __restrict__ Cf, int ldC, size_t sC, int Ktot)
{
    extern __shared__ __align__(1024) char smem[];
    const uint32_t su = smem_u32(smem);
    const int tid  = threadIdx.x;
    const int wid  = tid >> 5;
    const int lane = tid & 31;
    const int z    = blockIdx.z;

    Ah += (size_t)z * sA;  Al += (size_t)z * sA;
    Bh += (size_t)z * sB;  Bl += (size_t)z * sB;

    const __nv_bfloat16* gAh = Ah + (size_t)(blockIdx.y * 128) * ldA;
    const __nv_bfloat16* gAl = Al + (size_t)(blockIdx.y * 128) * ldA;
    const __nv_bfloat16* gBh = Bh + (size_t)(blockIdx.x * 128) * ldB;
    const __nv_bfloat16* gBl = Bl + (size_t)(blockIdx.x * 128) * ldB;

    // ---- cp.async loader: 128 rows x 4 x 16B segs per array, 2 per thread ----
    const int seg = tid & 3;       // 16B segment (8 bf16) within 64B row
    const int r0  = tid >> 2;      // rows r0, r0+64
    auto issue_chunk = [&](int k0, int buf) {
        const uint32_t base = su + (uint32_t)buf * BUF_B;
        #pragma unroll
        for (int i = 0; i < 2; i++) {
            const int r = r0 + 64 * i;
            const uint32_t so = sw_off(r, seg);
            const size_t oa = (size_t)r * ldA + k0 + seg * 8;
            const size_t ob = (size_t)r * ldB + k0 + seg * 8;
            cp16(base + 0 * ARR_B + so, gAh + oa);
            cp16(base + 1 * ARR_B + so, gAl + oa);
            cp16(base + 2 * ARR_B + so, gBh + ob);
            cp16(base + 3 * ARR_B + so, gBl + ob);
        }
    };

    // ---- warp tiling: 4 warps on M (32 rows each), 2 on N (64 cols each) ----
    const int warpM = (wid & 3) * 32;
    const int warpN = (wid >> 2) * 64;
    // ldmatrix lane roles
    const int laneA_row = lane & 15;          // + warpM + mt*16
    const int laneA_kh  = lane >> 4;          // k half (0/1)
    const int laneB_row = ((lane >> 4) << 3) + (lane & 7);  // + warpN + g*16
    const int laneB_kh  = (lane >> 3) & 1;

    float acc[2][8][4];
    #pragma unroll
    for (int mt = 0; mt < 2; mt++)
        #pragma unroll
        for (int nt = 0; nt < 8; nt++)
            #pragma unroll
            for (int e = 0; e < 4; e++) acc[mt][nt][e] = 0.f;

    const int nCh = Ktot / BK;   // >= 24 for all stages (>= INFLIGHT)

    // ---- prologue: put INFLIGHT chunks in flight ----
    #pragma unroll
    for (int s = 0; s < INFLIGHT; s++) {
        issue_chunk(s * BK, s % NBUF);
        CP_COMMIT();
    }

    for (int t = 0; t < nCh; t++) {
        // issue chunk t+INFLIGHT (or empty commit to keep group count uniform)
        if (t + INFLIGHT < nCh)
            issue_chunk((t + INFLIGHT) * BK, (t + INFLIGHT) % NBUF);
        CP_COMMIT();
        cp_wait<INFLIGHT>();   // chunk t's group retired (3 newer may pend)
        __syncthreads();       // all threads' groups for chunk t visible

        const uint32_t base = su + (uint32_t)(t % NBUF) * BUF_B;
        #pragma unroll
        for (int ks = 0; ks < 2; ks++) {
            // ---- hoist ALL fragment loads for this k16 step ----
            uint32_t aH[2][4], aL[2][4];
            #pragma unroll
            for (int mt = 0; mt < 2; mt++) {
                const int rA = warpM + mt * 16 + laneA_row;
                const int sA2 = ks * 2 + laneA_kh;
                ldsm4(aH[mt], base + 0 * ARR_B + sw_off(rA, sA2));
                ldsm4(aL[mt], base + 1 * ARR_B + sw_off(rA, sA2));
            }
            uint32_t bH[4][4], bL[4][4];
            #pragma unroll
            for (int g = 0; g < 4; g++) {
                const int rB = warpN + g * 16 + laneB_row;
                const int sB2 = ks * 2 + laneB_kh;
                ldsm4(bH[g], base + 2 * ARR_B + sw_off(rB, sB2));
                ldsm4(bL[g], base + 3 * ARR_B + sw_off(rB, sB2));
            }
            // ---- term 1: aH x bH — 16 MMAs, all distinct acc targets ----
            #pragma unroll
            for (int g = 0; g < 4; g++)
                #pragma unroll
                for (int mt = 0; mt < 2; mt++) {
                    mma16816(acc[mt][2 * g + 0], aH[mt], bH[g][0], bH[g][1]);
                    mma16816(acc[mt][2 * g + 1], aH[mt], bH[g][2], bH[g][3]);
                }
            // ---- term 2: aL x bH ----
            #pragma unroll
            for (int g = 0; g < 4; g++)
                #pragma unroll
                for (int mt = 0; mt < 2; mt++) {
                    mma16816(acc[mt][2 * g + 0], aL[mt], bH[g][0], bH[g][1]);
                    mma16816(acc[mt][2 * g + 1], aL[mt], bH[g][2], bH[g][3]);
                }
            // ---- term 3: aH x bL ----
            #pragma unroll
            for (int g = 0; g < 4; g++)
                #pragma unroll
                for (int mt = 0; mt < 2; mt++) {
                    mma16816(acc[mt][2 * g + 0], aH[mt], bL[g][0], bL[g][1]);
                    mma16816(acc[mt][2 * g + 1], aH[mt], bL[g][2], bL[g][3]);
                }
        }
        // NO trailing __syncthreads(): with NBUF=5 > INFLIGHT=3, the buffer
        // written by iteration t's issue (chunk t+3 -> buf (t-2)%5) was last
        // read at iteration t-2, and every warp reaching this point passed the
        // iteration t-1 barrier, which proves all warps finished iteration
        // t-2's compute.
    }

    // ---- epilogue: frag (mt,nt): rows warpM+mt*16+(lane>>2)(+8), cols +0/1 ----
    const int erow = lane >> 2;
    const int ecol = (lane & 3) * 2;
    #pragma unroll
    for (int mt = 0; mt < 2; mt++) {
        #pragma unroll
        for (int half = 0; half < 2; half++) {        // d01 (row) / d23 (row+8)
            const size_t mg = (size_t)blockIdx.y * 128 + warpM + mt * 16 + erow + half * 8;
            const float rowbias = (MODE == 1) ? bias[mg] : 0.f;
            #pragma unroll
            for (int nt = 0; nt < 8; nt++) {
                const int n0 = blockIdx.x * 128 + warpN + nt * 8 + ecol;
                float x0 = acc[mt][nt][half * 2 + 0];
                float x1 = acc[mt][nt][half * 2 + 1];
                if (MODE == 2) {
                    float2 v; v.x = x0; v.y = x1;
                    *(float2*)(Cf + (size_t)z * sC + mg * ldC + n0) = v;
                } else {
                    if (MODE == 0) {
                        x0 = (x0 + bias[n0 + 0]) * alpha;
                        x1 = (x1 + bias[n0 + 1]) * alpha;
                    } else {
                        x0 = (x0 + rowbias) * alpha;
                        x1 = (x1 + rowbias) * alpha;
                    }
                    __nv_bfloat16 h0, h1, l0, l1;
                    split2(x0, h0, l0); split2(x1, h1, l1);
                    __nv_bfloat162 hv; hv.x = h0; hv.y = h1;
                    __nv_bfloat162 lv; lv.x = l0; lv.y = l1;
                    *(__nv_bfloat162*)(Ch + (size_t)z * sC + mg * ldC + n0) = hv;
                    *(__nv_bfloat162*)(Cl + (size_t)z * sC + mg * ldC + n0) = lv;
                }
            }
        }
    }
}

// ============================================================================
// softmax over rows of g_S (fp32), writes split-bf16 P
// ============================================================================
__global__ __launch_bounds__(256)
void softmax_k(const float* __restrict__ S, __nv_bfloat16* __restrict__ Ph,
               __nv_bfloat16* __restrict__ Pl)
{
    __shared__ float red[8];
    __shared__ float resv;
    const int tid = threadIdx.x;
    const float* row = S + (size_t)blockIdx.x * SEQ;

    float4 a = *(const float4*)(row + tid * 8);
    float4 b = *(const float4*)(row + tid * 8 + 4);
    float v[8] = {a.x, a.y, a.z, a.w, b.x, b.y, b.z, b.w};

    float m = v[0];
    #pragma unroll
    for (int i = 1; i < 8; i++) m = fmaxf(m, v[i]);
    #pragma unroll
    for (int o = 16; o; o >>= 1) m = fmaxf(m, __shfl_xor_sync(0xffffffffu, m, o));
    if ((tid & 31) == 0) red[tid >> 5] = m;
    __syncthreads();
    if (tid == 0) {
        float t = red[0];
        #pragma unroll
        for (int w = 1; w < 8; w++) t = fmaxf(t, red[w]);
        resv = t;
    }
    __syncthreads();
    m = resv;

    float s = 0.f;
    #pragma unroll
    for (int i = 0; i < 8; i++) { v[i] = __expf(v[i] - m); s += v[i]; }
    #pragma unroll
    for (int o = 16; o; o >>= 1) s += __shfl_xor_sync(0xffffffffu, s, o);
    __syncthreads();
    if ((tid & 31) == 0) red[tid >> 5] = s;
    __syncthreads();
    if (tid == 0) {
        float t = 0.f;
        #pragma unroll
        for (int w = 0; w < 8; w++) t += red[w];
        resv = t;
    }
    __syncthreads();
    const float inv = 1.f / resv;

    __nv_bfloat16 hh[8], ll[8];
    #pragma unroll
    for (int i = 0; i < 8; i++) split2(v[i] * inv, hh[i], ll[i]);
    uint4 hv, lv;
    __nv_bfloat162 t0, t1, t2, t3;
    t0.x = hh[0]; t0.y = hh[1]; t1.x = hh[2]; t1.y = hh[3];
    t2.x = hh[4]; t2.y = hh[5]; t3.x = hh[6]; t3.y = hh[7];
    hv.x = *(uint32_t*)&t0; hv.y = *(uint32_t*)&t1;
    hv.z = *(uint32_t*)&t2; hv.w = *(uint32_t*)&t3;
    t0.x = ll[0]; t0.y = ll[1]; t1.x = ll[2]; t1.y = ll[3];
    t2.x = ll[4]; t2.y = ll[5]; t3.x = ll[6]; t3.y = ll[7];
    lv.x = *(uint32_t*)&t0; lv.y = *(uint32_t*)&t1;
    lv.z = *(uint32_t*)&t2; lv.w = *(uint32_t*)&t3;
    *(uint4*)(Ph + (size_t)blockIdx.x * SEQ + tid * 8) = hv;
    *(uint4*)(Pl + (size_t)blockIdx.x * SEQ + tid * 8) = lv;
}

// ============================================================================
extern "C" void kernel_launch(void* const* d_in, const int* in_sizes, int n_in,
                              void* d_out, int out_size)
{
    (void)in_sizes; (void)n_in; (void)out_size;
    const float* Z  = (const float*)d_in[0];
    const float* Wq = (const float*)d_in[1];
    const float* bq = (const float*)d_in[2];
    const float* Wk = (const float*)d_in[3];
    const float* bk = (const float*)d_in[4];
    const float* Wv = (const float*)d_in[5];
    const float* bv = (const float*)d_in[6];
    float* out = (float*)d_out;

    __nv_bfloat16 *Zh, *Zl, *Wh, *Wl, *Qh, *Ql, *Kh, *Kl, *Vth, *Vtl, *Ph, *Pl;
    float* Sc;
    cudaGetSymbolAddress((void**)&Zh,  g_Zh);
    cudaGetSymbolAddress((void**)&Zl,  g_Zl);
    cudaGetSymbolAddress((void**)&Wh,  g_Wh);
    cudaGetSymbolAddress((void**)&Wl,  g_Wl);
    cudaGetSymbolAddress((void**)&Qh,  g_Qh);
    cudaGetSymbolAddress((void**)&Ql,  g_Ql);
    cudaGetSymbolAddress((void**)&Kh,  g_Kh);
    cudaGetSymbolAddress((void**)&Kl,  g_Kl);
    cudaGetSymbolAddress((void**)&Vth, g_Vth);
    cudaGetSymbolAddress((void**)&Vtl, g_Vtl);
    cudaGetSymbolAddress((void**)&Ph,  g_Ph);
    cudaGetSymbolAddress((void**)&Pl,  g_Pl);
    cudaGetSymbolAddress((void**)&Sc,  g_S);

    cudaFuncSetAttribute(mma_gemm<0>, cudaFuncAttributeMaxDynamicSharedMemorySize, SMEM_BYTES);
    cudaFuncSetAttribute(mma_gemm<1>, cudaFuncAttributeMaxDynamicSharedMemorySize, SMEM_BYTES);
    cudaFuncSetAttribute(mma_gemm<2>, cudaFuncAttributeMaxDynamicSharedMemorySize, SMEM_BYTES);

    const float scale = 1.f / sqrtf((float)DIM);
    const size_t WSZ = (size_t)DIM * DIM;

    // 0) split inputs to bf16 hi/lo
    {
        int n4 = (MROWS * DIM) / 4;
        split_k<<<(n4 + 255) / 256, 256>>>((const float4*)Z,
            (__nv_bfloat162*)Zh, (__nv_bfloat162*)Zl, n4);
        int w4 = (DIM * DIM) / 4;
        split_k<<<(w4 + 255) / 256, 256>>>((const float4*)Wq,
            (__nv_bfloat162*)(Wh + 0 * WSZ), (__nv_bfloat162*)(Wl + 0 * WSZ), w4);
        split_k<<<(w4 + 255) / 256, 256>>>((const float4*)Wk,
            (__nv_bfloat162*)(Wh + 1 * WSZ), (__nv_bfloat162*)(Wl + 1 * WSZ), w4);
        split_k<<<(w4 + 255) / 256, 256>>>((const float4*)Wv,
            (__nv_bfloat162*)(Wh + 2 * WSZ), (__nv_bfloat162*)(Wl + 2 * WSZ), w4);
    }

    // 1) Q' = (Z Wq^T + bq)*scale ; K = Z Wk^T + bk   [mode 0]
    {
        dim3 g(DIM / 128, MROWS / 128, 1);
        mma_gemm<0><<<g, 256, SMEM_BYTES>>>(Zh, Zl, DIM, 0,
            Wh + 0 * WSZ, Wl + 0 * WSZ, DIM, 0, bq, scale,
            Qh, Ql, nullptr, DIM, 0, DIM);
        mma_gemm<0><<<g, 256, SMEM_BYTES>>>(Zh, Zl, DIM, 0,
            Wh + 1 * WSZ, Wl + 1 * WSZ, DIM, 0, bk, 1.f,
            Kh, Kl, nullptr, DIM, 0, DIM);
    }
    // 1v) Vt = Wv Z^T + bv[row]   [mode 1], Vt is [768, 16384]
    {
        dim3 g(MROWS / 128, DIM / 128, 1);
        mma_gemm<1><<<g, 256, SMEM_BYTES>>>(Wh + 2 * WSZ, Wl + 2 * WSZ, DIM, 0,
            Zh, Zl, DIM, 0, bv, 1.f,
            Vth, Vtl, nullptr, MROWS, 0, DIM);
    }
    // 2) scores = Q' K^T          [mode 2, fp32]
    {
        dim3 g(SEQ / 128, SEQ / 128, BATCH);
        mma_gemm<2><<<g, 256, SMEM_BYTES>>>(Qh, Ql, DIM, (size_t)SEQ * DIM,
            Kh, Kl, DIM, (size_t)SEQ * DIM, nullptr, 1.f,
            nullptr, nullptr, Sc, SEQ, (size_t)SEQ * SEQ, DIM);
    }
    // 3) softmax -> split-bf16 P
    softmax_k<<<BATCH * SEQ, 256>>>(Sc, Ph, Pl);

    // 4) out = P (Vt)^T           [mode 2, fp32]; batch selects Vt column band
    {
        dim3 g(DIM / 128, SEQ / 128, BATCH);
        mma_gemm<2><<<g, 256, SMEM_BYTES>>>(Ph, Pl, SEQ, (size_t)SEQ * SEQ,
            Vth, Vtl, MROWS, (size_t)SEQ, nullptr, 1.f,
            nullptr, nullptr, out, DIM, (size_t)SEQ * DIM, SEQ);
    }
}

// round 9
// speedup vs baseline: 3.0306x; 1.0860x over previous
#include <cuda_runtime.h>
#include <cuda_bf16.h>
#include <cstdint>
#include <math.h>

// ============================================================================
// SelfAttention B=8, S=2048, D=768 fp32 — bf16 split (hi/lo, 3-term) on the
// legacy tensor path (mma.sync.m16n8k16.bf16 + ldmatrix + cp.async).
// R9: 2 CTAs/SM co-residency. NBUF=3 / INFLIGHT=2 -> 96 KB smem, so two CTAs
//     overlap each other's barrier/wait/epilogue gaps on the tensor pipe.
//     Chunk issue moved AFTER the barrier (required for NBUF=3 safety).
//     Inner loop = R7 interleaved form (lower register pressure, order is
//     perf-neutral per R8 and numerically identical per-acc).
// ============================================================================

#define BATCH 8
#define SEQ   2048
#define DIM   768
#define MROWS (BATCH * SEQ)      // 16384
#define BK    32                 // k-chunk (32 bf16 = 64B rows)
#define ARR_B 8192               // 128 rows * 32 bf16 * 2B
#define BUF_B (4 * ARR_B)        // Ah, Al, Bh, Bl
#define NBUF  3                  // smem buffers
#define INFLIGHT 2               // cp.async chunks in flight
#define SMEM_BYTES (NBUF * BUF_B)   // 96 KB -> 2 CTAs/SM

// ---------------- device scratch (allocation-free rules) ----------------
__device__ __align__(256) __nv_bfloat16 g_Zh[(size_t)MROWS * DIM];
__device__ __align__(256) __nv_bfloat16 g_Zl[(size_t)MROWS * DIM];
__device__ __align__(256) __nv_bfloat16 g_Wh[3][(size_t)DIM * DIM];
__device__ __align__(256) __nv_bfloat16 g_Wl[3][(size_t)DIM * DIM];
__device__ __align__(256) __nv_bfloat16 g_Qh[(size_t)MROWS * DIM];
__device__ __align__(256) __nv_bfloat16 g_Ql[(size_t)MROWS * DIM];
__device__ __align__(256) __nv_bfloat16 g_Kh[(size_t)MROWS * DIM];
__device__ __align__(256) __nv_bfloat16 g_Kl[(size_t)MROWS * DIM];
__device__ __align__(256) __nv_bfloat16 g_Vth[(size_t)DIM * MROWS];  // [768,16384]
__device__ __align__(256) __nv_bfloat16 g_Vtl[(size_t)DIM * MROWS];
__device__ __align__(256) float         g_S [(size_t)BATCH * SEQ * SEQ];
__device__ __align__(256) __nv_bfloat16 g_Ph[(size_t)BATCH * SEQ * SEQ];
__device__ __align__(256) __nv_bfloat16 g_Pl[(size_t)BATCH * SEQ * SEQ];

// ---------------- PTX helpers (base ISA, compile at compute_100) --------
__device__ __forceinline__ uint32_t smem_u32(const void* p) {
    uint32_t a;
    asm("{ .reg .u64 t; cvta.to.shared.u64 t, %1; cvt.u32.u64 %0, t; }"
        : "=r"(a) : "l"(p));
    return a;
}
__device__ __forceinline__ void cp16(uint32_t saddr, const void* gaddr) {
    asm volatile("cp.async.cg.shared.global [%0], [%1], 16;"
                 :: "r"(saddr), "l"(gaddr));
}
#define CP_COMMIT() asm volatile("cp.async.commit_group;" ::: "memory")
template<int N>
__device__ __forceinline__ void cp_wait() {
    asm volatile("cp.async.wait_group %0;" :: "n"(N) : "memory");
}
__device__ __forceinline__ void ldsm4(uint32_t* r, uint32_t addr) {
    asm volatile("ldmatrix.sync.aligned.m8n8.x4.shared.b16 {%0,%1,%2,%3}, [%4];"
                 : "=r"(r[0]), "=r"(r[1]), "=r"(r[2]), "=r"(r[3]) : "r"(addr));
}
__device__ __forceinline__ void mma16816(float* d, const uint32_t* a,
                                         uint32_t b0, uint32_t b1) {
    asm volatile(
        "mma.sync.aligned.m16n8k16.row.col.f32.bf16.bf16.f32 "
        "{%0,%1,%2,%3}, {%4,%5,%6,%7}, {%8,%9}, {%0,%1,%2,%3};"
        : "+f"(d[0]), "+f"(d[1]), "+f"(d[2]), "+f"(d[3])
        : "r"(a[0]), "r"(a[1]), "r"(a[2]), "r"(a[3]), "r"(b0), "r"(b1));
}

// ---------------- split helpers ----------------
__device__ __forceinline__ void split2(float x, __nv_bfloat16& h, __nv_bfloat16& l) {
    h = __float2bfloat16(x);
    l = __float2bfloat16(x - __bfloat162float(h));
}

__global__ __launch_bounds__(256)
void split_k(const float4* __restrict__ in, __nv_bfloat162* __restrict__ h,
             __nv_bfloat162* __restrict__ l, int n4)
{
    int i = blockIdx.x * 256 + threadIdx.x;
    if (i >= n4) return;
    float4 x = in[i];
    __nv_bfloat16 h0, h1, h2, h3, l0, l1, l2, l3;
    split2(x.x, h0, l0); split2(x.y, h1, l1);
    split2(x.z, h2, l2); split2(x.w, h3, l3);
    __nv_bfloat162 a; a.x = h0; a.y = h1;
    __nv_bfloat162 b; b.x = h2; b.y = h3;
    __nv_bfloat162 c; c.x = l0; c.y = l1;
    __nv_bfloat162 d; d.x = l2; d.y = l3;
    h[2 * i] = a; h[2 * i + 1] = b;
    l[2 * i] = c; l[2 * i + 1] = d;
}

// swizzled smem offset for 64B rows: seg' = seg ^ ((row>>1)&3)
__device__ __forceinline__ uint32_t sw_off(int row, int seg) {
    return (uint32_t)row * 64u + (uint32_t)((seg ^ ((row >> 1) & 3)) * 16);
}

// ============================================================================
// split-bf16 NT GEMM: C[M,N] = (Ah+Al)[M,K] x ((Bh+Bl)[N,K])^T
// MODE 0: C -> bf16 hi/lo, x = (acc + bias[col]) * alpha
// MODE 1: C -> bf16 hi/lo, x = (acc + bias[row]) * alpha
// MODE 2: C -> fp32,        x = acc
// ============================================================================
template<int MODE>
__global__ __launch_bounds__(256, 2)
void mma_gemm(const __nv_bfloat16* __restrict__ Ah, const __nv_bfloat16* __restrict__ Al,
              int ldA, size_t sA,
              const __nv_bfloat16* __restrict__ Bh, const __nv_bfloat16* __restrict__ Bl,
              int ldB, size_t sB,
              const float* __restrict__ bias, float alpha,
              __nv_bfloat16* __restrict__ Ch, __nv_bfloat16* __restrict__ Cl,
              float* __restrict__ Cf, int ldC, size_t sC, int Ktot)
{
    extern __shared__ __align__(1024) char smem[];
    const uint32_t su = smem_u32(smem);
    const int tid  = threadIdx.x;
    const int wid  = tid >> 5;
    const int lane = tid & 31;
    const int z    = blockIdx.z;

    Ah += (size_t)z * sA;  Al += (size_t)z * sA;
    Bh += (size_t)z * sB;  Bl += (size_t)z * sB;

    const __nv_bfloat16* gAh = Ah + (size_t)(blockIdx.y * 128) * ldA;
    const __nv_bfloat16* gAl = Al + (size_t)(blockIdx.y * 128) * ldA;
    const __nv_bfloat16* gBh = Bh + (size_t)(blockIdx.x * 128) * ldB;
    const __nv_bfloat16* gBl = Bl + (size_t)(blockIdx.x * 128) * ldB;

    // ---- cp.async loader: 128 rows x 4 x 16B segs per array, 2 per thread ----
    const int seg = tid & 3;       // 16B segment (8 bf16) within 64B row
    const int r0  = tid >> 2;      // rows r0, r0+64
    auto issue_chunk = [&](int k0, int buf) {
        const uint32_t base = su + (uint32_t)buf * BUF_B;
        #pragma unroll
        for (int i = 0; i < 2; i++) {
            const int r = r0 + 64 * i;
            const uint32_t so = sw_off(r, seg);
            const size_t oa = (size_t)r * ldA + k0 + seg * 8;
            const size_t ob = (size_t)r * ldB + k0 + seg * 8;
            cp16(base + 0 * ARR_B + so, gAh + oa);
            cp16(base + 1 * ARR_B + so, gAl + oa);
            cp16(base + 2 * ARR_B + so, gBh + ob);
            cp16(base + 3 * ARR_B + so, gBl + ob);
        }
    };

    // ---- warp tiling: 4 warps on M (32 rows each), 2 on N (64 cols each) ----
    const int warpM = (wid & 3) * 32;
    const int warpN = (wid >> 2) * 64;
    // ldmatrix lane roles
    const int laneA_row = lane & 15;          // + warpM + mt*16
    const int laneA_kh  = lane >> 4;          // k half (0/1)
    const int laneB_row = ((lane >> 4) << 3) + (lane & 7);  // + warpN + g*16
    const int laneB_kh  = (lane >> 3) & 1;

    float acc[2][8][4];
    #pragma unroll
    for (int mt = 0; mt < 2; mt++)
        #pragma unroll
        for (int nt = 0; nt < 8; nt++)
            #pragma unroll
            for (int e = 0; e < 4; e++) acc[mt][nt][e] = 0.f;

    const int nCh = Ktot / BK;   // >= 24 for all stages (>= INFLIGHT)

    // ---- prologue: put INFLIGHT chunks in flight ----
    #pragma unroll
    for (int s = 0; s < INFLIGHT; s++) {
        issue_chunk(s * BK, s % NBUF);
        CP_COMMIT();
    }

    for (int t = 0; t < nCh; t++) {
        cp_wait<INFLIGHT - 1>();  // chunk t retired (t+1 may pend)
        __syncthreads();          // all warps done with compute t-1; chunk t visible

        // issue chunk t+INFLIGHT AFTER the barrier: its buffer (t+2)%3 ==
        // (t-1)%3 was last read at iteration t-1, which the barrier above
        // proves is complete across all warps.
        if (t + INFLIGHT < nCh)
            issue_chunk((t + INFLIGHT) * BK, (t + INFLIGHT) % NBUF);
        CP_COMMIT();              // uniform group count (possibly empty)

        const uint32_t base = su + (uint32_t)(t % NBUF) * BUF_B;
        #pragma unroll
        for (int ks = 0; ks < 2; ks++) {
            uint32_t aH[2][4], aL[2][4];
            #pragma unroll
            for (int mt = 0; mt < 2; mt++) {
                const int rA = warpM + mt * 16 + laneA_row;
                const int sA2 = ks * 2 + laneA_kh;
                ldsm4(aH[mt], base + 0 * ARR_B + sw_off(rA, sA2));
                ldsm4(aL[mt], base + 1 * ARR_B + sw_off(rA, sA2));
            }
            #pragma unroll
            for (int g = 0; g < 4; g++) {
                uint32_t bH[4], bL[4];
                const int rB = warpN + g * 16 + laneB_row;
                const int sB2 = ks * 2 + laneB_kh;
                ldsm4(bH, base + 2 * ARR_B + sw_off(rB, sB2));
                ldsm4(bL, base + 3 * ARR_B + sw_off(rB, sB2));
                #pragma unroll
                for (int mt = 0; mt < 2; mt++) {
                    mma16816(acc[mt][2 * g + 0], aH[mt], bH[0], bH[1]);
                    mma16816(acc[mt][2 * g + 1], aH[mt], bH[2], bH[3]);
                    mma16816(acc[mt][2 * g + 0], aL[mt], bH[0], bH[1]);
                    mma16816(acc[mt][2 * g + 1], aL[mt], bH[2], bH[3]);
                    mma16816(acc[mt][2 * g + 0], aH[mt], bL[0], bL[1]);
                    mma16816(acc[mt][2 * g + 1], aH[mt], bL[2], bL[3]);
                }
            }
        }
    }

    // ---- epilogue: frag (mt,nt): rows warpM+mt*16+(lane>>2)(+8), cols +0/1 ----
    const int erow = lane >> 2;
    const int ecol = (lane & 3) * 2;
    #pragma unroll
    for (int mt = 0; mt < 2; mt++) {
        #pragma unroll
        for (int half = 0; half < 2; half++) {        // d01 (row) / d23 (row+8)
            const size_t mg = (size_t)blockIdx.y * 128 + warpM + mt * 16 + erow + half * 8;
            const float rowbias = (MODE == 1) ? bias[mg] : 0.f;
            #pragma unroll
            for (int nt = 0; nt < 8; nt++) {
                const int n0 = blockIdx.x * 128 + warpN + nt * 8 + ecol;
                float x0 = acc[mt][nt][half * 2 + 0];
                float x1 = acc[mt][nt][half * 2 + 1];
                if (MODE == 2) {
                    float2 v; v.x = x0; v.y = x1;
                    *(float2*)(Cf + (size_t)z * sC + mg * ldC + n0) = v;
                } else {
                    if (MODE == 0) {
                        x0 = (x0 + bias[n0 + 0]) * alpha;
                        x1 = (x1 + bias[n0 + 1]) * alpha;
                    } else {
                        x0 = (x0 + rowbias) * alpha;
                        x1 = (x1 + rowbias) * alpha;
                    }
                    __nv_bfloat16 h0, h1, l0, l1;
                    split2(x0, h0, l0); split2(x1, h1, l1);
                    __nv_bfloat162 hv; hv.x = h0; hv.y = h1;
                    __nv_bfloat162 lv; lv.x = l0; lv.y = l1;
                    *(__nv_bfloat162*)(Ch + (size_t)z * sC + mg * ldC + n0) = hv;
                    *(__nv_bfloat162*)(Cl + (size_t)z * sC + mg * ldC + n0) = lv;
                }
            }
        }
    }
}

// ============================================================================
// softmax over rows of g_S (fp32), writes split-bf16 P
// ============================================================================
__global__ __launch_bounds__(256)
void softmax_k(const float* __restrict__ S, __nv_bfloat16* __restrict__ Ph,
               __nv_bfloat16* __restrict__ Pl)
{
    __shared__ float red[8];
    __shared__ float resv;
    const int tid = threadIdx.x;
    const float* row = S + (size_t)blockIdx.x * SEQ;

    float4 a = *(const float4*)(row + tid * 8);
    float4 b = *(const float4*)(row + tid * 8 + 4);
    float v[8] = {a.x, a.y, a.z, a.w, b.x, b.y, b.z, b.w};

    float m = v[0];
    #pragma unroll
    for (int i = 1; i < 8; i++) m = fmaxf(m, v[i]);
    #pragma unroll
    for (int o = 16; o; o >>= 1) m = fmaxf(m, __shfl_xor_sync(0xffffffffu, m, o));
    if ((tid & 31) == 0) red[tid >> 5] = m;
    __syncthreads();
    if (tid == 0) {
        float t = red[0];
        #pragma unroll
        for (int w = 1; w < 8; w++) t = fmaxf(t, red[w]);
        resv = t;
    }
    __syncthreads();
    m = resv;

    float s = 0.f;
    #pragma unroll
    for (int i = 0; i < 8; i++) { v[i] = __expf(v[i] - m); s += v[i]; }
    #pragma unroll
    for (int o = 16; o; o >>= 1) s += __shfl_xor_sync(0xffffffffu, s, o);
    __syncthreads();
    if ((tid & 31) == 0) red[tid >> 5] = s;
    __syncthreads();
    if (tid == 0) {
        float t = 0.f;
        #pragma unroll
        for (int w = 0; w < 8; w++) t += red[w];
        resv = t;
    }
    __syncthreads();
    const float inv = 1.f / resv;

    __nv_bfloat16 hh[8], ll[8];
    #pragma unroll
    for (int i = 0; i < 8; i++) split2(v[i] * inv, hh[i], ll[i]);
    uint4 hv, lv;
    __nv_bfloat162 t0, t1, t2, t3;
    t0.x = hh[0]; t0.y = hh[1]; t1.x = hh[2]; t1.y = hh[3];
    t2.x = hh[4]; t2.y = hh[5]; t3.x = hh[6]; t3.y = hh[7];
    hv.x = *(uint32_t*)&t0; hv.y = *(uint32_t*)&t1;
    hv.z = *(uint32_t*)&t2; hv.w = *(uint32_t*)&t3;
    t0.x = ll[0]; t0.y = ll[1]; t1.x = ll[2]; t1.y = ll[3];
    t2.x = ll[4]; t2.y = ll[5]; t3.x = ll[6]; t3.y = ll[7];
    lv.x = *(uint32_t*)&t0; lv.y = *(uint32_t*)&t1;
    lv.z = *(uint32_t*)&t2; lv.w = *(uint32_t*)&t3;
    *(uint4*)(Ph + (size_t)blockIdx.x * SEQ + tid * 8) = hv;
    *(uint4*)(Pl + (size_t)blockIdx.x * SEQ + tid * 8) = lv;
}

// ============================================================================
extern "C" void kernel_launch(void* const* d_in, const int* in_sizes, int n_in,
                              void* d_out, int out_size)
{
    (void)in_sizes; (void)n_in; (void)out_size;
    const float* Z  = (const float*)d_in[0];
    const float* Wq = (const float*)d_in[1];
    const float* bq = (const float*)d_in[2];
    const float* Wk = (const float*)d_in[3];
    const float* bk = (const float*)d_in[4];
    const float* Wv = (const float*)d_in[5];
    const float* bv = (const float*)d_in[6];
    float* out = (float*)d_out;

    __nv_bfloat16 *Zh, *Zl, *Wh, *Wl, *Qh, *Ql, *Kh, *Kl, *Vth, *Vtl, *Ph, *Pl;
    float* Sc;
    cudaGetSymbolAddress((void**)&Zh,  g_Zh);
    cudaGetSymbolAddress((void**)&Zl,  g_Zl);
    cudaGetSymbolAddress((void**)&Wh,  g_Wh);
    cudaGetSymbolAddress((void**)&Wl,  g_Wl);
    cudaGetSymbolAddress((void**)&Qh,  g_Qh);
    cudaGetSymbolAddress((void**)&Ql,  g_Ql);
    cudaGetSymbolAddress((void**)&Kh,  g_Kh);
    cudaGetSymbolAddress((void**)&Kl,  g_Kl);
    cudaGetSymbolAddress((void**)&Vth, g_Vth);
    cudaGetSymbolAddress((void**)&Vtl, g_Vtl);
    cudaGetSymbolAddress((void**)&Ph,  g_Ph);
    cudaGetSymbolAddress((void**)&Pl,  g_Pl);
    cudaGetSymbolAddress((void**)&Sc,  g_S);

    cudaFuncSetAttribute(mma_gemm<0>, cudaFuncAttributeMaxDynamicSharedMemorySize, SMEM_BYTES);
    cudaFuncSetAttribute(mma_gemm<1>, cudaFuncAttributeMaxDynamicSharedMemorySize, SMEM_BYTES);
    cudaFuncSetAttribute(mma_gemm<2>, cudaFuncAttributeMaxDynamicSharedMemorySize, SMEM_BYTES);

    const float scale = 1.f / sqrtf((float)DIM);
    const size_t WSZ = (size_t)DIM * DIM;

    // 0) split inputs to bf16 hi/lo
    {
        int n4 = (MROWS * DIM) / 4;
        split_k<<<(n4 + 255) / 256, 256>>>((const float4*)Z,
            (__nv_bfloat162*)Zh, (__nv_bfloat162*)Zl, n4);
        int w4 = (DIM * DIM) / 4;
        split_k<<<(w4 + 255) / 256, 256>>>((const float4*)Wq,
            (__nv_bfloat162*)(Wh + 0 * WSZ), (__nv_bfloat162*)(Wl + 0 * WSZ), w4);
        split_k<<<(w4 + 255) / 256, 256>>>((const float4*)Wk,
            (__nv_bfloat162*)(Wh + 1 * WSZ), (__nv_bfloat162*)(Wl + 1 * WSZ), w4);
        split_k<<<(w4 + 255) / 256, 256>>>((const float4*)Wv,
            (__nv_bfloat162*)(Wh + 2 * WSZ), (__nv_bfloat162*)(Wl + 2 * WSZ), w4);
    }

    // 1) Q' = (Z Wq^T + bq)*scale ; K = Z Wk^T + bk   [mode 0]
    {
        dim3 g(DIM / 128, MROWS / 128, 1);
        mma_gemm<0><<<g, 256, SMEM_BYTES>>>(Zh, Zl, DIM, 0,
            Wh + 0 * WSZ, Wl + 0 * WSZ, DIM, 0, bq, scale,
            Qh, Ql, nullptr, DIM, 0, DIM);
        mma_gemm<0><<<g, 256, SMEM_BYTES>>>(Zh, Zl, DIM, 0,
            Wh + 1 * WSZ, Wl + 1 * WSZ, DIM, 0, bk, 1.f,
            Kh, Kl, nullptr, DIM, 0, DIM);
    }
    // 1v) Vt = Wv Z^T + bv[row]   [mode 1], Vt is [768, 16384]
    {
        dim3 g(MROWS / 128, DIM / 128, 1);
        mma_gemm<1><<<g, 256, SMEM_BYTES>>>(Wh + 2 * WSZ, Wl + 2 * WSZ, DIM, 0,
            Zh, Zl, DIM, 0, bv, 1.f,
            Vth, Vtl, nullptr, MROWS, 0, DIM);
    }
    // 2) scores = Q' K^T          [mode 2, fp32]
    {
        dim3 g(SEQ / 128, SEQ / 128, BATCH);
        mma_gemm<2><<<g, 256, SMEM_BYTES>>>(Qh, Ql, DIM, (size_t)SEQ * DIM,
            Kh, Kl, DIM, (size_t)SEQ * DIM, nullptr, 1.f,
            nullptr, nullptr, Sc, SEQ, (size_t)SEQ * SEQ, DIM);
    }
    // 3) softmax -> split-bf16 P
    softmax_k<<<BATCH * SEQ, 256>>>(Sc, Ph, Pl);

    // 4) out = P (Vt)^T           [mode 2, fp32]; batch selects Vt column band
    {
        dim3 g(DIM / 128, SEQ / 128, BATCH);
        mma_gemm<2><<<g, 256, SMEM_BYTES>>>(Ph, Pl, SEQ, (size_t)SEQ * SEQ,
            Vth, Vtl, MROWS, (size_t)SEQ, nullptr, 1.f,
            nullptr, nullptr, out, DIM, (size_t)SEQ * DIM, SEQ);
    }
}